// round 12
// baseline (speedup 1.0000x reference)
#include <cuda_runtime.h>
#include <cuda_bf16.h>
#include <math.h>
#include <stdint.h>

#define BB 2
#define SS 2048
#define DM 1024
#define HH 16
#define DK 64
#define BSROWS (BB*SS)      // 4096
#define QKVN (3*DM)         // 3072

// ===========================================================================
// Scratch (allocation-free rule: __device__ globals). Everything bf16 hi/lo.
// ===========================================================================
__device__ __align__(16) __nv_bfloat16 x_hi[(size_t)BSROWS*DM];
__device__ __align__(16) __nv_bfloat16 x_lo[(size_t)BSROWS*DM];
__device__ __align__(16) __nv_bfloat16 wq_hi[(size_t)QKVN*DM];
__device__ __align__(16) __nv_bfloat16 wq_lo[(size_t)QKVN*DM];
__device__ __align__(16) __nv_bfloat16 wo_hi[(size_t)DM*DM];
__device__ __align__(16) __nv_bfloat16 wo_lo[(size_t)DM*DM];
__device__ __align__(16) __nv_bfloat16 q_hi[(size_t)BB*HH*SS*DK];
__device__ __align__(16) __nv_bfloat16 q_lo[(size_t)BB*HH*SS*DK];
__device__ __align__(16) __nv_bfloat16 k_hi[(size_t)BB*HH*SS*DK];
__device__ __align__(16) __nv_bfloat16 k_lo[(size_t)BB*HH*SS*DK];
__device__ __align__(16) __nv_bfloat16 v_hi[(size_t)BB*HH*SS*DK];
__device__ __align__(16) __nv_bfloat16 v_lo[(size_t)BB*HH*SS*DK];
__device__ __align__(16) __nv_bfloat16 att_hi[(size_t)BSROWS*DM];
__device__ __align__(16) __nv_bfloat16 att_lo[(size_t)BSROWS*DM];

// ===========================================================================
// PTX helpers
// ===========================================================================
__device__ __forceinline__ uint32_t smem_u32(const void* p) {
    uint32_t a;
    asm("{ .reg .u64 t; cvta.to.shared.u64 t, %1; cvt.u32.u64 %0, t; }" : "=r"(a) : "l"(p));
    return a;
}
__device__ __forceinline__ void ldsm_x4(uint32_t* r, uint32_t addr) {
    asm volatile("ldmatrix.sync.aligned.m8n8.x4.shared.b16 {%0,%1,%2,%3}, [%4];"
                 : "=r"(r[0]), "=r"(r[1]), "=r"(r[2]), "=r"(r[3]) : "r"(addr));
}
__device__ __forceinline__ void ldsm_x4t(uint32_t* r, uint32_t addr) {
    asm volatile("ldmatrix.sync.aligned.m8n8.x4.trans.shared.b16 {%0,%1,%2,%3}, [%4];"
                 : "=r"(r[0]), "=r"(r[1]), "=r"(r[2]), "=r"(r[3]) : "r"(addr));
}
__device__ __forceinline__ void mma16816(float* d, const uint32_t* a, const uint32_t* b) {
    asm volatile("mma.sync.aligned.m16n8k16.row.col.f32.bf16.bf16.f32 "
                 "{%0,%1,%2,%3}, {%4,%5,%6,%7}, {%8,%9}, {%0,%1,%2,%3};"
                 : "+f"(d[0]), "+f"(d[1]), "+f"(d[2]), "+f"(d[3])
                 : "r"(a[0]), "r"(a[1]), "r"(a[2]), "r"(a[3]), "r"(b[0]), "r"(b[1]));
}
__device__ __forceinline__ void cp16(uint32_t saddr, const void* g) {
    asm volatile("cp.async.cg.shared.global [%0], [%1], 16;" :: "r"(saddr), "l"(g));
}
#define CP_COMMIT() asm volatile("cp.async.commit_group;" ::: "memory")
#define CP_WAIT1()  asm volatile("cp.async.wait_group 1;" ::: "memory")
#define CP_WAIT0()  asm volatile("cp.async.wait_group 0;" ::: "memory")

__device__ __forceinline__ uint32_t bf2u(__nv_bfloat16 a, __nv_bfloat16 b) {
    __nv_bfloat162 t; t.x = a; t.y = b;
    return *reinterpret_cast<uint32_t*>(&t);
}
__device__ __forceinline__ void cvt_hl(float4 v, uint2& hi, uint2& lo) {
    __nv_bfloat16 h0 = __float2bfloat16_rn(v.x);
    __nv_bfloat16 h1 = __float2bfloat16_rn(v.y);
    __nv_bfloat16 h2 = __float2bfloat16_rn(v.z);
    __nv_bfloat16 h3 = __float2bfloat16_rn(v.w);
    __nv_bfloat16 l0 = __float2bfloat16_rn(v.x - __bfloat162float(h0));
    __nv_bfloat16 l1 = __float2bfloat16_rn(v.y - __bfloat162float(h1));
    __nv_bfloat16 l2 = __float2bfloat16_rn(v.z - __bfloat162float(h2));
    __nv_bfloat16 l3 = __float2bfloat16_rn(v.w - __bfloat162float(h3));
    hi = make_uint2(bf2u(h0, h1), bf2u(h2, h3));
    lo = make_uint2(bf2u(l0, l1), bf2u(l2, l3));
}
__device__ __forceinline__ void split2(float a, float b, uint32_t& hi, uint32_t& lo) {
    __nv_bfloat16 h0 = __float2bfloat16_rn(a);
    __nv_bfloat16 h1 = __float2bfloat16_rn(b);
    __nv_bfloat16 l0 = __float2bfloat16_rn(a - __bfloat162float(h0));
    __nv_bfloat16 l1 = __float2bfloat16_rn(b - __bfloat162float(h1));
    hi = bf2u(h0, h1);
    lo = bf2u(l0, l1);
}

// ===========================================================================
// Convert: split x / qkv_w / out_w fp32 -> bf16 hi/lo
// ===========================================================================
#define N4_X  (BSROWS*DM/4)
#define N4_WQ (QKVN*DM/4)
#define N4_WO (DM*DM/4)
#define N4_TOTAL (N4_X + N4_WQ + N4_WO)

__global__ __launch_bounds__(256)
void cvt_split_kernel(const float* __restrict__ x, const float* __restrict__ wq,
                      const float* __restrict__ wo) {
    int i = blockIdx.x * blockDim.x + threadIdx.x;
    const float4* s; uint2 *dh, *dl; int j;
    if (i < N4_X)                  { j = i;                 s = (const float4*)x;  dh = (uint2*)x_hi;  dl = (uint2*)x_lo; }
    else if (i < N4_X + N4_WQ)     { j = i - N4_X;          s = (const float4*)wq; dh = (uint2*)wq_hi; dl = (uint2*)wq_lo; }
    else                           { j = i - N4_X - N4_WQ;  s = (const float4*)wo; dh = (uint2*)wo_hi; dl = (uint2*)wo_lo; }
    float4 v = s[j];
    uint2 h, l;
    cvt_hl(v, h, l);
    dh[j] = h; dl[j] = l;
}

// ===========================================================================
// bf16x3 GEMM via mma.sync + cp.async. C[M,N] = A[M,1024] @ B[N,1024]^T.
// CTA tile 256x128, 512 threads (16 warps, 4m x 4n, warp tile 64x32),
// K-chunk 32, 3-stage cp.async ring, single barrier per chunk.
// TERM-MAJOR mma ordering: dependent accumulator reuse at distance 8.
// MODE 0: store fp32 C. MODE 1: fused RoPE epilogue -> q/k/v hi/lo.
// ===========================================================================
#define KC 32
#define LDAS 40
#define OFF_AHI 0
#define OFF_ALO 20480                   // 256*40*2
#define OFF_BHI 40960
#define OFF_BLO 51200                   // +128*40*2
#define STAGE_B 61440
#define GEMM_SMEM (3*STAGE_B)           // 184320
#define KLOG 0.28782313662f             // 2/64 * ln(10000)

template<int MODE>
__global__ __launch_bounds__(512, 1)
void gemm_bf16x3_kernel(const __nv_bfloat16* __restrict__ Ahi, const __nv_bfloat16* __restrict__ Alo,
                        const __nv_bfloat16* __restrict__ Bhi, const __nv_bfloat16* __restrict__ Blo,
                        float* __restrict__ C, const int* __restrict__ pos, int N) {
    extern __shared__ char smem[];
    const uint32_t sbase = smem_u32(smem);
    const int tid  = threadIdx.x;
    const int wid  = tid >> 5;
    const int lane = tid & 31;
    const int m0 = blockIdx.y * 256;
    const int n0 = blockIdx.x * 128;
    const int wm = wid & 3;          // 0..3 -> m slab of 64
    const int wn = wid >> 2;         // 0..3 -> n slab of 32

    const uint4* Ah4 = (const uint4*)Ahi;
    const uint4* Al4 = (const uint4*)Alo;
    const uint4* Bh4 = (const uint4*)Bhi;
    const uint4* Bl4 = (const uint4*)Blo;

    auto issue = [&](int c, int s) {
        const int k0 = c * KC;
        const uint32_t sb0 = sbase + s * STAGE_B;
#pragma unroll
        for (int it = 0; it < 2; it++) {
            int f = it * 512 + tid;
            int row = f >> 2;
            int ch  = (f & 3) * 8;
            size_t gi = ((size_t)(m0 + row) * DM + k0 + ch) >> 3;
            uint32_t so = sb0 + (uint32_t)(row * LDAS + ch) * 2;
            cp16(so + OFF_AHI, Ah4 + gi);
            cp16(so + OFF_ALO, Al4 + gi);
        }
        {
            int row = tid >> 2;
            int ch  = (tid & 3) * 8;
            size_t gj = ((size_t)(n0 + row) * DM + k0 + ch) >> 3;
            uint32_t so = sb0 + (uint32_t)(row * LDAS + ch) * 2;
            cp16(so + OFF_BHI, Bh4 + gj);
            cp16(so + OFF_BLO, Bl4 + gj);
        }
    };

    const int gg   = lane >> 3;
    const int arow = (lane & 7) + ((lane >> 3) & 1) * 8;
    const int acol = (lane >> 4) * 8;
    const int b4row = ((gg >> 1) & 1) * 8 + (lane & 7);
    const int b4col = (gg & 1) * 8;

    float acc[4][4][4];
#pragma unroll
    for (int mi = 0; mi < 4; mi++)
#pragma unroll
        for (int ni = 0; ni < 4; ni++)
#pragma unroll
            for (int q = 0; q < 4; q++) acc[mi][ni][q] = 0.0f;

    const int nch = DM / KC;   // 32
    issue(0, 0); CP_COMMIT();
    issue(1, 1); CP_COMMIT();

    int stg_i = 0;
    for (int c = 0; c < nch; c++) {
        if (c + 1 < nch) CP_WAIT1(); else CP_WAIT0();
        __syncthreads();
        if (c + 2 < nch) { issue(c + 2, (stg_i + 2) % 3); CP_COMMIT(); }

        const uint32_t stg = sbase + stg_i * STAGE_B;
#pragma unroll
        for (int ks = 0; ks < 2; ks++) {
            uint32_t ah[4][4], al[4][4];
#pragma unroll
            for (int mi = 0; mi < 4; mi++) {
                uint32_t eoff = ((wm * 64 + mi * 16 + arow) * LDAS + ks * 16 + acol) * 2;
                ldsm_x4(ah[mi], stg + OFF_AHI + eoff);
                ldsm_x4(al[mi], stg + OFF_ALO + eoff);
            }
#pragma unroll
            for (int n2 = 0; n2 < 2; n2++) {
                uint32_t bhf[4], blf[4];
                uint32_t eoff = ((wn * 32 + n2 * 16 + b4row) * LDAS + ks * 16 + b4col) * 2;
                ldsm_x4(bhf, stg + OFF_BHI + eoff);
                ldsm_x4(blf, stg + OFF_BLO + eoff);
                // term-major: 8 independent mmas per group
#pragma unroll
                for (int mi = 0; mi < 4; mi++) {
                    mma16816(acc[mi][n2 * 2],     ah[mi], bhf);
                    mma16816(acc[mi][n2 * 2 + 1], ah[mi], bhf + 2);
                }
#pragma unroll
                for (int mi = 0; mi < 4; mi++) {
                    mma16816(acc[mi][n2 * 2],     ah[mi], blf);
                    mma16816(acc[mi][n2 * 2 + 1], ah[mi], blf + 2);
                }
#pragma unroll
                for (int mi = 0; mi < 4; mi++) {
                    mma16816(acc[mi][n2 * 2],     al[mi], bhf);
                    mma16816(acc[mi][n2 * 2 + 1], al[mi], bhf + 2);
                }
            }
        }
        stg_i = (stg_i + 1) % 3;
    }

    const int crow = lane >> 2;
    const int ccol = (lane & 3) * 2;

    if (MODE == 0) {
#pragma unroll
        for (int mi = 0; mi < 4; mi++) {
            const size_t r0 = (size_t)(m0 + wm * 64 + mi * 16 + crow);
#pragma unroll
            for (int ni = 0; ni < 4; ni++) {
                const int cc = n0 + wn * 32 + ni * 8 + ccol;
                *(float2*)(C + r0 * N + cc)       = make_float2(acc[mi][ni][0], acc[mi][ni][1]);
                *(float2*)(C + (r0 + 8) * N + cc) = make_float2(acc[mi][ni][2], acc[mi][ni][3]);
            }
        }
    } else {
        const int sec  = n0 >> 10;
        const int nmod = n0 & 1023;
        int hh_[4], ii_[4];
        float ifr_[4];
#pragma unroll
        for (int ni = 0; ni < 4; ni++) {
            int colmod = nmod + wn * 32 + ni * 8 + ccol;
            hh_[ni] = colmod >> 6;
            ii_[ni] = (colmod & 63) >> 1;
            ifr_[ni] = (sec < 2) ? expf(-(float)ii_[ni] * KLOG) : 0.0f;
        }
        uint32_t* ghi = (sec == 0) ? (uint32_t*)q_hi : (sec == 1) ? (uint32_t*)k_hi : (uint32_t*)v_hi;
        uint32_t* glo = (sec == 0) ? (uint32_t*)q_lo : (sec == 1) ? (uint32_t*)k_lo : (uint32_t*)v_lo;
#pragma unroll
        for (int mi = 0; mi < 4; mi++) {
            const int rbase = m0 + wm * 64 + mi * 16 + crow;
#pragma unroll
            for (int half = 0; half < 2; half++) {
                const int r = rbase + half * 8;
                const int p = pos[r];
                const int b = r >> 11;
                const int s = r & 2047;
#pragma unroll
                for (int ni = 0; ni < 4; ni++) {
                    float v0 = acc[mi][ni][half * 2];
                    float v1 = acc[mi][ni][half * 2 + 1];
                    float o0, o1;
                    if (sec < 2) {
                        float ang = (float)p * ifr_[ni];
                        float cs = cosf(ang), sn = sinf(ang);
                        o0 = v0 * cs - v1 * sn;
                        o1 = v0 * sn + v1 * cs;
                        if (sec == 0) { o0 *= 0.125f; o1 *= 0.125f; }
                    } else { o0 = v0; o1 = v1; }
                    uint32_t hi, lo;
                    split2(o0, o1, hi, lo);
                    size_t idx = ((size_t)(b * HH + hh_[ni]) * SS + s) * 32 + ii_[ni];
                    ghi[idx] = hi;
                    glo[idx] = lo;
                }
            }
        }
    }
}

// ===========================================================================
// Tensor-core causal flash attention (bf16x3), pre-split q/k/v, 3-stage
// cp.async KV ring, single barrier per tile, TERM-MAJOR mma ordering.
// ===========================================================================
#define AT_LDS 72
#define AT_STG 36864                    // KV stage: Khi,Klo,Vhi,Vlo @ 9216
#define AT_QHI (3*AT_STG)               // 110592
#define AT_QLO (AT_QHI + 18432)
#define ATT_SMEM (AT_QLO + 18432)       // 147456

__global__ __launch_bounds__(256)
void attn_tc_kernel() {
    extern __shared__ char smem[];
    const uint32_t sb = smem_u32(smem);
    const int tid  = threadIdx.x;
    const int wid  = tid >> 5;
    const int lane = tid & 31;
    const int bh = blockIdx.y;
    const int qt = gridDim.x - 1 - blockIdx.x;   // heavy tiles first
    const int qbase = qt * 128;

    const uint4* qh4 = (const uint4*)q_hi + (size_t)bh * SS * 8;
    const uint4* ql4 = (const uint4*)q_lo + (size_t)bh * SS * 8;
    const uint4* kh4 = (const uint4*)k_hi + (size_t)bh * SS * 8;
    const uint4* kl4 = (const uint4*)k_lo + (size_t)bh * SS * 8;
    const uint4* vh4 = (const uint4*)v_hi + (size_t)bh * SS * 8;
    const uint4* vl4 = (const uint4*)v_lo + (size_t)bh * SS * 8;

    // ---- load Q tile 128x64 hi/lo ----
#pragma unroll
    for (int it = 0; it < 4; it++) {
        int f = it * 256 + tid;
        int row = f >> 3;
        int ch  = f & 7;
        uint32_t so = (uint32_t)(row * AT_LDS + ch * 8) * 2;
        *(uint4*)(smem + AT_QHI + so) = qh4[(size_t)(qbase + row) * 8 + ch];
        *(uint4*)(smem + AT_QLO + so) = ql4[(size_t)(qbase + row) * 8 + ch];
    }
    __syncthreads();

    const int gg   = lane >> 3;
    const int arow = (lane & 7) + ((lane >> 3) & 1) * 8;
    const int acol = (lane >> 4) * 8;
    const int b4row = ((gg >> 1) & 1) * 8 + (lane & 7);
    const int b4col = (gg & 1) * 8;
    const int v4row = (gg & 1) * 8 + (lane & 7);
    const int v4col = (gg >> 1) * 8;

    uint32_t qh[4][4], ql[4][4];
#pragma unroll
    for (int ks = 0; ks < 4; ks++) {
        uint32_t eoff = ((wid * 16 + arow) * AT_LDS + ks * 16 + acol) * 2;
        ldsm_x4(qh[ks], sb + AT_QHI + eoff);
        ldsm_x4(ql[ks], sb + AT_QLO + eoff);
    }

    float o[8][4];
#pragma unroll
    for (int ni = 0; ni < 8; ni++)
#pragma unroll
        for (int q = 0; q < 4; q++) o[ni][q] = 0.0f;
    float m0 = -INFINITY, m1 = -INFINITY, l0 = 0.0f, l1 = 0.0f;

    const int g  = lane >> 2;
    const int qq = lane & 3;
    const int row0 = qbase + wid * 16 + g;
    const int warp_maxrow = qbase + wid * 16 + 15;

    auto kv_issue = [&](int t, int s) {
        const int kvb = t * 64;
#pragma unroll
        for (int it = 0; it < 2; it++) {
            int f = it * 256 + tid;
            int row = f >> 3;
            int ch  = f & 7;
            uint32_t so = sb + s * AT_STG + (uint32_t)(row * AT_LDS + ch * 8) * 2;
            size_t gi = (size_t)(kvb + row) * 8 + ch;
            cp16(so,         kh4 + gi);
            cp16(so +  9216, kl4 + gi);
            cp16(so + 18432, vh4 + gi);
            cp16(so + 27648, vl4 + gi);
        }
    };

    const int ntiles = (qt + 1) * 2;
    kv_issue(0, 0); CP_COMMIT();
    if (ntiles > 1) { kv_issue(1, 1); CP_COMMIT(); }

    int stg_i = 0;
    for (int t = 0; t < ntiles; t++) {
        if (t + 1 < ntiles) CP_WAIT1(); else CP_WAIT0();
        __syncthreads();
        if (t + 2 < ntiles) { kv_issue(t + 2, (stg_i + 2) % 3); CP_COMMIT(); }

        const int kvb = t * 64;
        const uint32_t stg = sb + stg_i * AT_STG;

        if (kvb <= warp_maxrow) {
            // ---- S = Q @ K^T (3-term, term-major per ks) ----
            float s[8][4];
#pragma unroll
            for (int ni = 0; ni < 8; ni++)
#pragma unroll
                for (int q = 0; q < 4; q++) s[ni][q] = 0.0f;
#pragma unroll
            for (int ks = 0; ks < 4; ks++) {
                uint32_t khf[4][4], klf[4][4];
#pragma unroll
                for (int n2 = 0; n2 < 4; n2++) {
                    uint32_t eoff = ((n2 * 16 + b4row) * AT_LDS + ks * 16 + b4col) * 2;
                    ldsm_x4(khf[n2], stg + eoff);
                    ldsm_x4(klf[n2], stg + 9216 + eoff);
                }
#pragma unroll
                for (int n2 = 0; n2 < 4; n2++) {
                    mma16816(s[n2 * 2],     qh[ks], khf[n2]);
                    mma16816(s[n2 * 2 + 1], qh[ks], khf[n2] + 2);
                }
#pragma unroll
                for (int n2 = 0; n2 < 4; n2++) {
                    mma16816(s[n2 * 2],     qh[ks], klf[n2]);
                    mma16816(s[n2 * 2 + 1], qh[ks], klf[n2] + 2);
                }
#pragma unroll
                for (int n2 = 0; n2 < 4; n2++) {
                    mma16816(s[n2 * 2],     ql[ks], khf[n2]);
                    mma16816(s[n2 * 2 + 1], ql[ks], khf[n2] + 2);
                }
            }

            // ---- causal mask ----
            if (kvb + 63 > qbase + wid * 16) {
#pragma unroll
                for (int ni = 0; ni < 8; ni++) {
                    int c = kvb + ni * 8 + qq * 2;
                    if (c     > row0)     s[ni][0] = -INFINITY;
                    if (c + 1 > row0)     s[ni][1] = -INFINITY;
                    if (c     > row0 + 8) s[ni][2] = -INFINITY;
                    if (c + 1 > row0 + 8) s[ni][3] = -INFINITY;
                }
            }

            // ---- online softmax ----
            float t0 = -INFINITY, t1 = -INFINITY;
#pragma unroll
            for (int ni = 0; ni < 8; ni++) {
                t0 = fmaxf(t0, fmaxf(s[ni][0], s[ni][1]));
                t1 = fmaxf(t1, fmaxf(s[ni][2], s[ni][3]));
            }
            t0 = fmaxf(t0, __shfl_xor_sync(0xFFFFFFFF, t0, 1));
            t0 = fmaxf(t0, __shfl_xor_sync(0xFFFFFFFF, t0, 2));
            t1 = fmaxf(t1, __shfl_xor_sync(0xFFFFFFFF, t1, 1));
            t1 = fmaxf(t1, __shfl_xor_sync(0xFFFFFFFF, t1, 2));
            float nm0 = fmaxf(m0, t0), nm1 = fmaxf(m1, t1);
            float sc0 = __expf(m0 - nm0), sc1 = __expf(m1 - nm1);
            m0 = nm0; m1 = nm1;
            l0 *= sc0; l1 *= sc1;
#pragma unroll
            for (int ni = 0; ni < 8; ni++) {
                o[ni][0] *= sc0; o[ni][1] *= sc0;
                o[ni][2] *= sc1; o[ni][3] *= sc1;
            }

            // ---- P = exp(S - m) -> bf16 hi/lo fragments ----
            uint32_t ph[8][2], pl[8][2];
            float rs0 = 0.0f, rs1 = 0.0f;
#pragma unroll
            for (int ni = 0; ni < 8; ni++) {
                float p0 = __expf(s[ni][0] - m0);
                float p1 = __expf(s[ni][1] - m0);
                float p2 = __expf(s[ni][2] - m1);
                float p3 = __expf(s[ni][3] - m1);
                rs0 += p0 + p1;
                rs1 += p2 + p3;
                split2(p0, p1, ph[ni][0], pl[ni][0]);
                split2(p2, p3, ph[ni][1], pl[ni][1]);
            }
            rs0 += __shfl_xor_sync(0xFFFFFFFF, rs0, 1);
            rs0 += __shfl_xor_sync(0xFFFFFFFF, rs0, 2);
            rs1 += __shfl_xor_sync(0xFFFFFFFF, rs1, 1);
            rs1 += __shfl_xor_sync(0xFFFFFFFF, rs1, 2);
            l0 += rs0; l1 += rs1;

            // ---- O += P @ V (3-term, term-major per kc) ----
#pragma unroll
            for (int kc = 0; kc < 4; kc++) {
                uint32_t ah[4] = { ph[2*kc][0], ph[2*kc][1], ph[2*kc+1][0], ph[2*kc+1][1] };
                uint32_t al[4] = { pl[2*kc][0], pl[2*kc][1], pl[2*kc+1][0], pl[2*kc+1][1] };
                uint32_t vhf[4][4], vlf[4][4];
#pragma unroll
                for (int n2 = 0; n2 < 4; n2++) {
                    uint32_t eoff = ((kc * 16 + v4row) * AT_LDS + n2 * 16 + v4col) * 2;
                    ldsm_x4t(vhf[n2], stg + 18432 + eoff);
                    ldsm_x4t(vlf[n2], stg + 27648 + eoff);
                }
#pragma unroll
                for (int n2 = 0; n2 < 4; n2++) {
                    mma16816(o[n2 * 2],     ah, vhf[n2]);
                    mma16816(o[n2 * 2 + 1], ah, vhf[n2] + 2);
                }
#pragma unroll
                for (int n2 = 0; n2 < 4; n2++) {
                    mma16816(o[n2 * 2],     ah, vlf[n2]);
                    mma16816(o[n2 * 2 + 1], ah, vlf[n2] + 2);
                }
#pragma unroll
                for (int n2 = 0; n2 < 4; n2++) {
                    mma16816(o[n2 * 2],     al, vhf[n2]);
                    mma16816(o[n2 * 2 + 1], al, vhf[n2] + 2);
                }
            }
        }
        stg_i = (stg_i + 1) % 3;
    }

    // ---- epilogue: normalize + split -> att_hi/att_lo ----
    const float inv0 = 1.0f / l0;
    const float inv1 = 1.0f / l1;
    const int b = bh / HH;
    const int h = bh % HH;
    uint32_t* ahi32 = (uint32_t*)att_hi;
    uint32_t* alo32 = (uint32_t*)att_lo;
    const size_t base0 = ((size_t)b * SS + row0) * 512 + h * 32;
    const size_t base1 = ((size_t)b * SS + row0 + 8) * 512 + h * 32;
#pragma unroll
    for (int ni = 0; ni < 8; ni++) {
        uint32_t hi, lo;
        split2(o[ni][0] * inv0, o[ni][1] * inv0, hi, lo);
        ahi32[base0 + ni * 4 + qq] = hi;
        alo32[base0 + ni * 4 + qq] = lo;
        split2(o[ni][2] * inv1, o[ni][3] * inv1, hi, lo);
        ahi32[base1 + ni * 4 + qq] = hi;
        alo32[base1 + ni * 4 + qq] = lo;
    }
}

// ===========================================================================
extern "C" void kernel_launch(void* const* d_in, const int* in_sizes, int n_in,
                              void* d_out, int out_size) {
    const float* x     = (const float*)d_in[0];
    const int*   pos   = (const int*)d_in[1];
    const float* qkv_w = (const float*)d_in[2];
    const float* out_w = (const float*)d_in[3];
    float* out = (float*)d_out;

    __nv_bfloat16 *p_xhi, *p_xlo, *p_wqhi, *p_wqlo, *p_wohi, *p_wolo, *p_ahi, *p_alo;
    cudaGetSymbolAddress((void**)&p_xhi,  x_hi);
    cudaGetSymbolAddress((void**)&p_xlo,  x_lo);
    cudaGetSymbolAddress((void**)&p_wqhi, wq_hi);
    cudaGetSymbolAddress((void**)&p_wqlo, wq_lo);
    cudaGetSymbolAddress((void**)&p_wohi, wo_hi);
    cudaGetSymbolAddress((void**)&p_wolo, wo_lo);
    cudaGetSymbolAddress((void**)&p_ahi,  att_hi);
    cudaGetSymbolAddress((void**)&p_alo,  att_lo);

    cudaFuncSetAttribute(gemm_bf16x3_kernel<0>, cudaFuncAttributeMaxDynamicSharedMemorySize, GEMM_SMEM);
    cudaFuncSetAttribute(gemm_bf16x3_kernel<1>, cudaFuncAttributeMaxDynamicSharedMemorySize, GEMM_SMEM);
    cudaFuncSetAttribute(attn_tc_kernel,        cudaFuncAttributeMaxDynamicSharedMemorySize, ATT_SMEM);

    // 0) fp32 -> bf16 hi/lo for x, qkv_w, out_w
    cvt_split_kernel<<<N4_TOTAL / 256, 256>>>(x, qkv_w, out_w);

    // 1) QKV projection + fused RoPE -> q/k/v hi/lo
    gemm_bf16x3_kernel<1><<<dim3(QKVN / 128, BSROWS / 256), 512, GEMM_SMEM>>>(
        p_xhi, p_xlo, p_wqhi, p_wqlo, nullptr, pos, QKVN);

    // 2) Causal flash attention -> att hi/lo
    attn_tc_kernel<<<dim3(SS / 128, BB * HH), 256, ATT_SMEM>>>();

    // 3) Output projection -> fp32 out
    gemm_bf16x3_kernel<0><<<dim3(DM / 128, BSROWS / 256), 512, GEMM_SMEM>>>(
        p_ahi, p_alo, p_wohi, p_wolo, out, nullptr, DM);
}

// round 13
// speedup vs baseline: 1.2860x; 1.2860x over previous
#include <cuda_runtime.h>
#include <cuda_fp16.h>
#include <math.h>
#include <stdint.h>

#define BB 2
#define SS 2048
#define DM 1024
#define HH 16
#define DK 64
#define BSROWS (BB*SS)      // 4096
#define QKVN (3*DM)         // 3072

// ===========================================================================
// Scratch (allocation-free rule: __device__ globals). fp16: activations split
// hi/lo, stationary operands (weights, K, V) single-rounded.
// ===========================================================================
__device__ __align__(16) __half x_hi[(size_t)BSROWS*DM];
__device__ __align__(16) __half x_lo[(size_t)BSROWS*DM];
__device__ __align__(16) __half wq_f[(size_t)QKVN*DM];
__device__ __align__(16) __half wo_f[(size_t)DM*DM];
__device__ __align__(16) __half q_hi[(size_t)BB*HH*SS*DK];
__device__ __align__(16) __half q_lo[(size_t)BB*HH*SS*DK];
__device__ __align__(16) __half k_f[(size_t)BB*HH*SS*DK];
__device__ __align__(16) __half v_f[(size_t)BB*HH*SS*DK];
__device__ __align__(16) __half att_hi[(size_t)BSROWS*DM];
__device__ __align__(16) __half att_lo[(size_t)BSROWS*DM];

// ===========================================================================
// PTX helpers
// ===========================================================================
__device__ __forceinline__ uint32_t smem_u32(const void* p) {
    uint32_t a;
    asm("{ .reg .u64 t; cvta.to.shared.u64 t, %1; cvt.u32.u64 %0, t; }" : "=r"(a) : "l"(p));
    return a;
}
__device__ __forceinline__ void ldsm_x4(uint32_t* r, uint32_t addr) {
    asm volatile("ldmatrix.sync.aligned.m8n8.x4.shared.b16 {%0,%1,%2,%3}, [%4];"
                 : "=r"(r[0]), "=r"(r[1]), "=r"(r[2]), "=r"(r[3]) : "r"(addr));
}
__device__ __forceinline__ void ldsm_x4t(uint32_t* r, uint32_t addr) {
    asm volatile("ldmatrix.sync.aligned.m8n8.x4.trans.shared.b16 {%0,%1,%2,%3}, [%4];"
                 : "=r"(r[0]), "=r"(r[1]), "=r"(r[2]), "=r"(r[3]) : "r"(addr));
}
__device__ __forceinline__ void mma16816(float* d, const uint32_t* a, const uint32_t* b) {
    asm volatile("mma.sync.aligned.m16n8k16.row.col.f32.f16.f16.f32 "
                 "{%0,%1,%2,%3}, {%4,%5,%6,%7}, {%8,%9}, {%0,%1,%2,%3};"
                 : "+f"(d[0]), "+f"(d[1]), "+f"(d[2]), "+f"(d[3])
                 : "r"(a[0]), "r"(a[1]), "r"(a[2]), "r"(a[3]), "r"(b[0]), "r"(b[1]));
}
__device__ __forceinline__ void cp16(uint32_t saddr, const void* g) {
    asm volatile("cp.async.cg.shared.global [%0], [%1], 16;" :: "r"(saddr), "l"(g));
}
#define CP_COMMIT() asm volatile("cp.async.commit_group;" ::: "memory")
#define CP_WAIT1()  asm volatile("cp.async.wait_group 1;" ::: "memory")
#define CP_WAIT0()  asm volatile("cp.async.wait_group 0;" ::: "memory")

__device__ __forceinline__ uint32_t h2u(__half a, __half b) {
    __half2 t; t.x = a; t.y = b;
    return *reinterpret_cast<uint32_t*>(&t);
}
// split float4 into fp16 hi/lo packed pairs
__device__ __forceinline__ void cvt_hl(float4 v, uint2& hi, uint2& lo) {
    __half h0 = __float2half_rn(v.x), h1 = __float2half_rn(v.y);
    __half h2 = __float2half_rn(v.z), h3 = __float2half_rn(v.w);
    __half l0 = __float2half_rn(v.x - __half2float(h0));
    __half l1 = __float2half_rn(v.y - __half2float(h1));
    __half l2 = __float2half_rn(v.z - __half2float(h2));
    __half l3 = __float2half_rn(v.w - __half2float(h3));
    hi = make_uint2(h2u(h0, h1), h2u(h2, h3));
    lo = make_uint2(h2u(l0, l1), h2u(l2, l3));
}
// single-round float4 -> 4 fp16
__device__ __forceinline__ uint2 cvt_h4(float4 v) {
    return make_uint2(h2u(__float2half_rn(v.x), __float2half_rn(v.y)),
                      h2u(__float2half_rn(v.z), __float2half_rn(v.w)));
}
__device__ __forceinline__ void split2(float a, float b, uint32_t& hi, uint32_t& lo) {
    __half h0 = __float2half_rn(a), h1 = __float2half_rn(b);
    __half l0 = __float2half_rn(a - __half2float(h0));
    __half l1 = __float2half_rn(b - __half2float(h1));
    hi = h2u(h0, h1);
    lo = h2u(l0, l1);
}

// ===========================================================================
// Convert: x -> fp16 hi/lo; wq, wo -> single fp16
// ===========================================================================
#define N4_X  (BSROWS*DM/4)
#define N4_WQ (QKVN*DM/4)
#define N4_WO (DM*DM/4)
#define N4_TOTAL (N4_X + N4_WQ + N4_WO)

__global__ __launch_bounds__(256)
void cvt_split_kernel(const float* __restrict__ x, const float* __restrict__ wq,
                      const float* __restrict__ wo) {
    int i = blockIdx.x * blockDim.x + threadIdx.x;
    if (i < N4_X) {
        float4 v = ((const float4*)x)[i];
        uint2 h, l;
        cvt_hl(v, h, l);
        ((uint2*)x_hi)[i] = h;
        ((uint2*)x_lo)[i] = l;
    } else if (i < N4_X + N4_WQ) {
        int j = i - N4_X;
        ((uint2*)wq_f)[j] = cvt_h4(((const float4*)wq)[j]);
    } else if (i < N4_TOTAL) {
        int j = i - N4_X - N4_WQ;
        ((uint2*)wo_f)[j] = cvt_h4(((const float4*)wo)[j]);
    }
}

// ===========================================================================
// fp16x2 GEMM via mma.sync + cp.async. C[M,N] = A[M,1024] @ B[N,1024]^T.
// A split hi/lo fp16, B single fp16 -> 2 mmas per product term.
// CTA tile 256x128, 512 threads (16 warps, 4m x 4n, warp tile 64x32),
// K-chunk 32, 3-stage cp.async ring, single barrier per chunk.
// MODE 0: store fp32 C. MODE 1: fused RoPE epilogue -> q hi/lo, k, v.
// ===========================================================================
#define KC 32
#define LDAS 40
#define OFF_AHI 0
#define OFF_ALO 20480                   // 256*40*2
#define OFF_B   40960                   // +128*40*2
#define STAGE_B 51200
#define GEMM_SMEM (3*STAGE_B)           // 153600
#define KLOG 0.28782313662f             // 2/64 * ln(10000)

template<int MODE>
__global__ __launch_bounds__(512, 1)
void gemm_fp16x2_kernel(const __half* __restrict__ Ahi, const __half* __restrict__ Alo,
                        const __half* __restrict__ Bf,
                        float* __restrict__ C, const int* __restrict__ pos, int N) {
    extern __shared__ char smem[];
    const uint32_t sbase = smem_u32(smem);
    const int tid  = threadIdx.x;
    const int wid  = tid >> 5;
    const int lane = tid & 31;
    const int m0 = blockIdx.y * 256;
    const int n0 = blockIdx.x * 128;
    const int wm = wid & 3;
    const int wn = wid >> 2;

    const uint4* Ah4 = (const uint4*)Ahi;
    const uint4* Al4 = (const uint4*)Alo;
    const uint4* Bh4 = (const uint4*)Bf;

    auto issue = [&](int c, int s) {
        const int k0 = c * KC;
        const uint32_t sb0 = sbase + s * STAGE_B;
#pragma unroll
        for (int it = 0; it < 2; it++) {
            int f = it * 512 + tid;
            int row = f >> 2;
            int ch  = (f & 3) * 8;
            size_t gi = ((size_t)(m0 + row) * DM + k0 + ch) >> 3;
            uint32_t so = sb0 + (uint32_t)(row * LDAS + ch) * 2;
            cp16(so + OFF_AHI, Ah4 + gi);
            cp16(so + OFF_ALO, Al4 + gi);
        }
        {
            int row = tid >> 2;
            int ch  = (tid & 3) * 8;
            size_t gj = ((size_t)(n0 + row) * DM + k0 + ch) >> 3;
            uint32_t so = sb0 + (uint32_t)(row * LDAS + ch) * 2;
            cp16(so + OFF_B, Bh4 + gj);
        }
    };

    const int gg   = lane >> 3;
    const int arow = (lane & 7) + ((lane >> 3) & 1) * 8;
    const int acol = (lane >> 4) * 8;
    const int b4row = ((gg >> 1) & 1) * 8 + (lane & 7);
    const int b4col = (gg & 1) * 8;

    float acc[4][4][4];
#pragma unroll
    for (int mi = 0; mi < 4; mi++)
#pragma unroll
        for (int ni = 0; ni < 4; ni++)
#pragma unroll
            for (int q = 0; q < 4; q++) acc[mi][ni][q] = 0.0f;

    const int nch = DM / KC;   // 32
    issue(0, 0); CP_COMMIT();
    issue(1, 1); CP_COMMIT();

    int stg_i = 0;
    for (int c = 0; c < nch; c++) {
        if (c + 1 < nch) CP_WAIT1(); else CP_WAIT0();
        __syncthreads();
        if (c + 2 < nch) { issue(c + 2, (stg_i + 2) % 3); CP_COMMIT(); }

        const uint32_t stg = sbase + stg_i * STAGE_B;
#pragma unroll
        for (int ks = 0; ks < 2; ks++) {
            uint32_t ah[4][4], al[4][4];
#pragma unroll
            for (int mi = 0; mi < 4; mi++) {
                uint32_t eoff = ((wm * 64 + mi * 16 + arow) * LDAS + ks * 16 + acol) * 2;
                ldsm_x4(ah[mi], stg + OFF_AHI + eoff);
                ldsm_x4(al[mi], stg + OFF_ALO + eoff);
            }
#pragma unroll
            for (int n2 = 0; n2 < 2; n2++) {
                uint32_t bhf[4];
                uint32_t eoff = ((wn * 32 + n2 * 16 + b4row) * LDAS + ks * 16 + b4col) * 2;
                ldsm_x4(bhf, stg + OFF_B + eoff);
#pragma unroll
                for (int mi = 0; mi < 4; mi++) {
                    mma16816(acc[mi][n2 * 2],     ah[mi], bhf);
                    mma16816(acc[mi][n2 * 2],     al[mi], bhf);
                    mma16816(acc[mi][n2 * 2 + 1], ah[mi], bhf + 2);
                    mma16816(acc[mi][n2 * 2 + 1], al[mi], bhf + 2);
                }
            }
        }
        stg_i = (stg_i + 1) % 3;
    }

    const int crow = lane >> 2;
    const int ccol = (lane & 3) * 2;

    if (MODE == 0) {
#pragma unroll
        for (int mi = 0; mi < 4; mi++) {
            const size_t r0 = (size_t)(m0 + wm * 64 + mi * 16 + crow);
#pragma unroll
            for (int ni = 0; ni < 4; ni++) {
                const int cc = n0 + wn * 32 + ni * 8 + ccol;
                *(float2*)(C + r0 * N + cc)       = make_float2(acc[mi][ni][0], acc[mi][ni][1]);
                *(float2*)(C + (r0 + 8) * N + cc) = make_float2(acc[mi][ni][2], acc[mi][ni][3]);
            }
        }
    } else {
        // fused RoPE: sec 0=q (rope*0.125, split hi/lo), 1=k (rope, single), 2=v (copy, single)
        const int sec  = n0 >> 10;
        const int nmod = n0 & 1023;
        int hh_[4], ii_[4];
        float ifr_[4];
#pragma unroll
        for (int ni = 0; ni < 4; ni++) {
            int colmod = nmod + wn * 32 + ni * 8 + ccol;
            hh_[ni] = colmod >> 6;
            ii_[ni] = (colmod & 63) >> 1;
            ifr_[ni] = (sec < 2) ? expf(-(float)ii_[ni] * KLOG) : 0.0f;
        }
        uint32_t* ghi = (sec == 0) ? (uint32_t*)q_hi : (sec == 1) ? (uint32_t*)k_f : (uint32_t*)v_f;
        uint32_t* glo = (uint32_t*)q_lo;
#pragma unroll
        for (int mi = 0; mi < 4; mi++) {
            const int rbase = m0 + wm * 64 + mi * 16 + crow;
#pragma unroll
            for (int half = 0; half < 2; half++) {
                const int r = rbase + half * 8;
                const int p = pos[r];
                const int b = r >> 11;
                const int s = r & 2047;
#pragma unroll
                for (int ni = 0; ni < 4; ni++) {
                    float v0 = acc[mi][ni][half * 2];
                    float v1 = acc[mi][ni][half * 2 + 1];
                    float o0, o1;
                    if (sec < 2) {
                        float ang = (float)p * ifr_[ni];
                        float cs = cosf(ang), sn = sinf(ang);
                        o0 = v0 * cs - v1 * sn;
                        o1 = v0 * sn + v1 * cs;
                        if (sec == 0) { o0 *= 0.125f; o1 *= 0.125f; }
                    } else { o0 = v0; o1 = v1; }
                    size_t idx = ((size_t)(b * HH + hh_[ni]) * SS + s) * 32 + ii_[ni];
                    if (sec == 0) {
                        uint32_t hi, lo;
                        split2(o0, o1, hi, lo);
                        ghi[idx] = hi;
                        glo[idx] = lo;
                    } else {
                        ghi[idx] = h2u(__float2half_rn(o0), __float2half_rn(o1));
                    }
                }
            }
        }
    }
}

// ===========================================================================
// Tensor-core causal flash attention (fp16x2): Q/P split hi/lo, K/V single.
// CTA = (bh, 128-q-tile), 8 warps x m16 slabs, kv tiles of 64,
// 3-stage cp.async KV ring, single barrier per tile.
// ===========================================================================
#define AT_LDS 72
#define AT_STG 18432                    // KV stage: Kf @0, Vf @9216
#define AT_QHI (3*AT_STG)               // 55296
#define AT_QLO (AT_QHI + 18432)
#define ATT_SMEM (AT_QLO + 18432)       // 92160

__global__ __launch_bounds__(256)
void attn_tc_kernel() {
    extern __shared__ char smem[];
    const uint32_t sb = smem_u32(smem);
    const int tid  = threadIdx.x;
    const int wid  = tid >> 5;
    const int lane = tid & 31;
    const int bh = blockIdx.y;
    const int qt = gridDim.x - 1 - blockIdx.x;   // heavy tiles first
    const int qbase = qt * 128;

    const uint4* qh4 = (const uint4*)q_hi + (size_t)bh * SS * 8;
    const uint4* ql4 = (const uint4*)q_lo + (size_t)bh * SS * 8;
    const uint4* kh4 = (const uint4*)k_f + (size_t)bh * SS * 8;
    const uint4* vh4 = (const uint4*)v_f + (size_t)bh * SS * 8;

    // ---- load Q tile 128x64 hi/lo ----
#pragma unroll
    for (int it = 0; it < 4; it++) {
        int f = it * 256 + tid;
        int row = f >> 3;
        int ch  = f & 7;
        uint32_t so = (uint32_t)(row * AT_LDS + ch * 8) * 2;
        *(uint4*)(smem + AT_QHI + so) = qh4[(size_t)(qbase + row) * 8 + ch];
        *(uint4*)(smem + AT_QLO + so) = ql4[(size_t)(qbase + row) * 8 + ch];
    }
    __syncthreads();

    const int gg   = lane >> 3;
    const int arow = (lane & 7) + ((lane >> 3) & 1) * 8;
    const int acol = (lane >> 4) * 8;
    const int b4row = ((gg >> 1) & 1) * 8 + (lane & 7);
    const int b4col = (gg & 1) * 8;
    const int v4row = (gg & 1) * 8 + (lane & 7);
    const int v4col = (gg >> 1) * 8;

    uint32_t qh[4][4], ql[4][4];
#pragma unroll
    for (int ks = 0; ks < 4; ks++) {
        uint32_t eoff = ((wid * 16 + arow) * AT_LDS + ks * 16 + acol) * 2;
        ldsm_x4(qh[ks], sb + AT_QHI + eoff);
        ldsm_x4(ql[ks], sb + AT_QLO + eoff);
    }

    float o[8][4];
#pragma unroll
    for (int ni = 0; ni < 8; ni++)
#pragma unroll
        for (int q = 0; q < 4; q++) o[ni][q] = 0.0f;
    float m0 = -INFINITY, m1 = -INFINITY, l0 = 0.0f, l1 = 0.0f;

    const int g  = lane >> 2;
    const int qq = lane & 3;
    const int row0 = qbase + wid * 16 + g;
    const int warp_maxrow = qbase + wid * 16 + 15;

    auto kv_issue = [&](int t, int s) {
        const int kvb = t * 64;
#pragma unroll
        for (int it = 0; it < 2; it++) {
            int f = it * 256 + tid;
            int row = f >> 3;
            int ch  = f & 7;
            uint32_t so = sb + s * AT_STG + (uint32_t)(row * AT_LDS + ch * 8) * 2;
            size_t gi = (size_t)(kvb + row) * 8 + ch;
            cp16(so,        kh4 + gi);
            cp16(so + 9216, vh4 + gi);
        }
    };

    const int ntiles = (qt + 1) * 2;
    kv_issue(0, 0); CP_COMMIT();
    if (ntiles > 1) { kv_issue(1, 1); CP_COMMIT(); }

    int stg_i = 0;
    for (int t = 0; t < ntiles; t++) {
        if (t + 1 < ntiles) CP_WAIT1(); else CP_WAIT0();
        __syncthreads();
        if (t + 2 < ntiles) { kv_issue(t + 2, (stg_i + 2) % 3); CP_COMMIT(); }

        const int kvb = t * 64;
        const uint32_t stg = sb + stg_i * AT_STG;

        if (kvb <= warp_maxrow) {
            // ---- S = Q @ K^T (2-term: qh,ql x K) ----
            float s[8][4];
#pragma unroll
            for (int ni = 0; ni < 8; ni++)
#pragma unroll
                for (int q = 0; q < 4; q++) s[ni][q] = 0.0f;
#pragma unroll
            for (int ks = 0; ks < 4; ks++) {
#pragma unroll
                for (int n2 = 0; n2 < 4; n2++) {
                    uint32_t khf[4];
                    uint32_t eoff = ((n2 * 16 + b4row) * AT_LDS + ks * 16 + b4col) * 2;
                    ldsm_x4(khf, stg + eoff);
                    mma16816(s[n2 * 2],     qh[ks], khf);
                    mma16816(s[n2 * 2],     ql[ks], khf);
                    mma16816(s[n2 * 2 + 1], qh[ks], khf + 2);
                    mma16816(s[n2 * 2 + 1], ql[ks], khf + 2);
                }
            }

            // ---- causal mask ----
            if (kvb + 63 > qbase + wid * 16) {
#pragma unroll
                for (int ni = 0; ni < 8; ni++) {
                    int c = kvb + ni * 8 + qq * 2;
                    if (c     > row0)     s[ni][0] = -INFINITY;
                    if (c + 1 > row0)     s[ni][1] = -INFINITY;
                    if (c     > row0 + 8) s[ni][2] = -INFINITY;
                    if (c + 1 > row0 + 8) s[ni][3] = -INFINITY;
                }
            }

            // ---- online softmax ----
            float t0 = -INFINITY, t1 = -INFINITY;
#pragma unroll
            for (int ni = 0; ni < 8; ni++) {
                t0 = fmaxf(t0, fmaxf(s[ni][0], s[ni][1]));
                t1 = fmaxf(t1, fmaxf(s[ni][2], s[ni][3]));
            }
            t0 = fmaxf(t0, __shfl_xor_sync(0xFFFFFFFF, t0, 1));
            t0 = fmaxf(t0, __shfl_xor_sync(0xFFFFFFFF, t0, 2));
            t1 = fmaxf(t1, __shfl_xor_sync(0xFFFFFFFF, t1, 1));
            t1 = fmaxf(t1, __shfl_xor_sync(0xFFFFFFFF, t1, 2));
            float nm0 = fmaxf(m0, t0), nm1 = fmaxf(m1, t1);
            float sc0 = __expf(m0 - nm0), sc1 = __expf(m1 - nm1);
            m0 = nm0; m1 = nm1;
            l0 *= sc0; l1 *= sc1;
#pragma unroll
            for (int ni = 0; ni < 8; ni++) {
                o[ni][0] *= sc0; o[ni][1] *= sc0;
                o[ni][2] *= sc1; o[ni][3] *= sc1;
            }

            // ---- P = exp(S - m) -> fp16 hi/lo fragments ----
            uint32_t ph[8][2], pl[8][2];
            float rs0 = 0.0f, rs1 = 0.0f;
#pragma unroll
            for (int ni = 0; ni < 8; ni++) {
                float p0 = __expf(s[ni][0] - m0);
                float p1 = __expf(s[ni][1] - m0);
                float p2 = __expf(s[ni][2] - m1);
                float p3 = __expf(s[ni][3] - m1);
                rs0 += p0 + p1;
                rs1 += p2 + p3;
                split2(p0, p1, ph[ni][0], pl[ni][0]);
                split2(p2, p3, ph[ni][1], pl[ni][1]);
            }
            rs0 += __shfl_xor_sync(0xFFFFFFFF, rs0, 1);
            rs0 += __shfl_xor_sync(0xFFFFFFFF, rs0, 2);
            rs1 += __shfl_xor_sync(0xFFFFFFFF, rs1, 1);
            rs1 += __shfl_xor_sync(0xFFFFFFFF, rs1, 2);
            l0 += rs0; l1 += rs1;

            // ---- O += P @ V (2-term: ph,pl x V) ----
#pragma unroll
            for (int kc = 0; kc < 4; kc++) {
                uint32_t ah[4] = { ph[2*kc][0], ph[2*kc][1], ph[2*kc+1][0], ph[2*kc+1][1] };
                uint32_t al[4] = { pl[2*kc][0], pl[2*kc][1], pl[2*kc+1][0], pl[2*kc+1][1] };
#pragma unroll
                for (int n2 = 0; n2 < 4; n2++) {
                    uint32_t vhf[4];
                    uint32_t eoff = ((kc * 16 + v4row) * AT_LDS + n2 * 16 + v4col) * 2;
                    ldsm_x4t(vhf, stg + 9216 + eoff);
                    mma16816(o[n2 * 2],     ah, vhf);
                    mma16816(o[n2 * 2],     al, vhf);
                    mma16816(o[n2 * 2 + 1], ah, vhf + 2);
                    mma16816(o[n2 * 2 + 1], al, vhf + 2);
                }
            }
        }
        stg_i = (stg_i + 1) % 3;
    }

    // ---- epilogue: normalize + split -> att_hi/att_lo ----
    const float inv0 = 1.0f / l0;
    const float inv1 = 1.0f / l1;
    const int b = bh / HH;
    const int h = bh % HH;
    uint32_t* ahi32 = (uint32_t*)att_hi;
    uint32_t* alo32 = (uint32_t*)att_lo;
    const size_t base0 = ((size_t)b * SS + row0) * 512 + h * 32;
    const size_t base1 = ((size_t)b * SS + row0 + 8) * 512 + h * 32;
#pragma unroll
    for (int ni = 0; ni < 8; ni++) {
        uint32_t hi, lo;
        split2(o[ni][0] * inv0, o[ni][1] * inv0, hi, lo);
        ahi32[base0 + ni * 4 + qq] = hi;
        alo32[base0 + ni * 4 + qq] = lo;
        split2(o[ni][2] * inv1, o[ni][3] * inv1, hi, lo);
        ahi32[base1 + ni * 4 + qq] = hi;
        alo32[base1 + ni * 4 + qq] = lo;
    }
}

// ===========================================================================
extern "C" void kernel_launch(void* const* d_in, const int* in_sizes, int n_in,
                              void* d_out, int out_size) {
    const float* x     = (const float*)d_in[0];
    const int*   pos   = (const int*)d_in[1];
    const float* qkv_w = (const float*)d_in[2];
    const float* out_w = (const float*)d_in[3];
    float* out = (float*)d_out;

    __half *p_xhi, *p_xlo, *p_wq, *p_wo, *p_ahi, *p_alo;
    cudaGetSymbolAddress((void**)&p_xhi, x_hi);
    cudaGetSymbolAddress((void**)&p_xlo, x_lo);
    cudaGetSymbolAddress((void**)&p_wq,  wq_f);
    cudaGetSymbolAddress((void**)&p_wo,  wo_f);
    cudaGetSymbolAddress((void**)&p_ahi, att_hi);
    cudaGetSymbolAddress((void**)&p_alo, att_lo);

    cudaFuncSetAttribute(gemm_fp16x2_kernel<0>, cudaFuncAttributeMaxDynamicSharedMemorySize, GEMM_SMEM);
    cudaFuncSetAttribute(gemm_fp16x2_kernel<1>, cudaFuncAttributeMaxDynamicSharedMemorySize, GEMM_SMEM);
    cudaFuncSetAttribute(attn_tc_kernel,        cudaFuncAttributeMaxDynamicSharedMemorySize, ATT_SMEM);

    // 0) fp32 -> fp16 (x split hi/lo; weights single)
    cvt_split_kernel<<<(N4_TOTAL + 255) / 256, 256>>>(x, qkv_w, out_w);

    // 1) QKV projection + fused RoPE -> q hi/lo, k, v
    gemm_fp16x2_kernel<1><<<dim3(QKVN / 128, BSROWS / 256), 512, GEMM_SMEM>>>(
        p_xhi, p_xlo, p_wq, nullptr, pos, QKVN);

    // 2) Causal flash attention -> att hi/lo
    attn_tc_kernel<<<dim3(SS / 128, BB * HH), 256, ATT_SMEM>>>();

    // 3) Output projection -> fp32 out
    gemm_fp16x2_kernel<0><<<dim3(DM / 128, BSROWS / 256), 512, GEMM_SMEM>>>(
        p_ahi, p_alo, p_wo, out, nullptr, DM);
}

// round 14
// speedup vs baseline: 1.9021x; 1.4791x over previous
#include <cuda_runtime.h>
#include <cuda_fp16.h>
#include <math.h>
#include <stdint.h>

#define BB 2
#define SS 2048
#define DM 1024
#define HH 16
#define DK 64
#define BSROWS (BB*SS)      // 4096
#define QKVN (3*DM)         // 3072

// ===========================================================================
// Scratch (allocation-free rule: __device__ globals).
// fp16 single-rounded: x, weights, k, v, att, P. fp16 hi/lo split: q only
// (softmax amplifies q rounding; everything else is plain relative error).
// ===========================================================================
__device__ __align__(16) __half x_f[(size_t)BSROWS*DM];
__device__ __align__(16) __half wq_f[(size_t)QKVN*DM];
__device__ __align__(16) __half wo_f[(size_t)DM*DM];
__device__ __align__(16) __half q_hi[(size_t)BB*HH*SS*DK];
__device__ __align__(16) __half q_lo[(size_t)BB*HH*SS*DK];
__device__ __align__(16) __half k_f[(size_t)BB*HH*SS*DK];
__device__ __align__(16) __half v_f[(size_t)BB*HH*SS*DK];
__device__ __align__(16) __half att_f[(size_t)BSROWS*DM];

// ===========================================================================
// PTX helpers
// ===========================================================================
__device__ __forceinline__ uint32_t smem_u32(const void* p) {
    uint32_t a;
    asm("{ .reg .u64 t; cvta.to.shared.u64 t, %1; cvt.u32.u64 %0, t; }" : "=r"(a) : "l"(p));
    return a;
}
__device__ __forceinline__ void ldsm_x4(uint32_t* r, uint32_t addr) {
    asm volatile("ldmatrix.sync.aligned.m8n8.x4.shared.b16 {%0,%1,%2,%3}, [%4];"
                 : "=r"(r[0]), "=r"(r[1]), "=r"(r[2]), "=r"(r[3]) : "r"(addr));
}
__device__ __forceinline__ void ldsm_x4t(uint32_t* r, uint32_t addr) {
    asm volatile("ldmatrix.sync.aligned.m8n8.x4.trans.shared.b16 {%0,%1,%2,%3}, [%4];"
                 : "=r"(r[0]), "=r"(r[1]), "=r"(r[2]), "=r"(r[3]) : "r"(addr));
}
__device__ __forceinline__ void mma16816(float* d, const uint32_t* a, const uint32_t* b) {
    asm volatile("mma.sync.aligned.m16n8k16.row.col.f32.f16.f16.f32 "
                 "{%0,%1,%2,%3}, {%4,%5,%6,%7}, {%8,%9}, {%0,%1,%2,%3};"
                 : "+f"(d[0]), "+f"(d[1]), "+f"(d[2]), "+f"(d[3])
                 : "r"(a[0]), "r"(a[1]), "r"(a[2]), "r"(a[3]), "r"(b[0]), "r"(b[1]));
}
__device__ __forceinline__ void cp16(uint32_t saddr, const void* g) {
    asm volatile("cp.async.cg.shared.global [%0], [%1], 16;" :: "r"(saddr), "l"(g));
}
#define CP_COMMIT() asm volatile("cp.async.commit_group;" ::: "memory")
#define CP_WAIT1()  asm volatile("cp.async.wait_group 1;" ::: "memory")
#define CP_WAIT0()  asm volatile("cp.async.wait_group 0;" ::: "memory")

__device__ __forceinline__ uint32_t h2u(__half a, __half b) {
    __half2 t; t.x = a; t.y = b;
    return *reinterpret_cast<uint32_t*>(&t);
}
__device__ __forceinline__ uint2 cvt_h4(float4 v) {
    return make_uint2(h2u(__float2half_rn(v.x), __float2half_rn(v.y)),
                      h2u(__float2half_rn(v.z), __float2half_rn(v.w)));
}
__device__ __forceinline__ void split2(float a, float b, uint32_t& hi, uint32_t& lo) {
    __half h0 = __float2half_rn(a), h1 = __float2half_rn(b);
    __half l0 = __float2half_rn(a - __half2float(h0));
    __half l1 = __float2half_rn(b - __half2float(h1));
    hi = h2u(h0, h1);
    lo = h2u(l0, l1);
}

// ===========================================================================
// Convert: x, wq, wo -> single fp16
// ===========================================================================
#define N4_X  (BSROWS*DM/4)
#define N4_WQ (QKVN*DM/4)
#define N4_WO (DM*DM/4)
#define N4_TOTAL (N4_X + N4_WQ + N4_WO)

__global__ __launch_bounds__(256)
void cvt_split_kernel(const float* __restrict__ x, const float* __restrict__ wq,
                      const float* __restrict__ wo) {
    int i = blockIdx.x * blockDim.x + threadIdx.x;
    if (i < N4_X) {
        ((uint2*)x_f)[i] = cvt_h4(((const float4*)x)[i]);
    } else if (i < N4_X + N4_WQ) {
        int j = i - N4_X;
        ((uint2*)wq_f)[j] = cvt_h4(((const float4*)wq)[j]);
    } else if (i < N4_TOTAL) {
        int j = i - N4_X - N4_WQ;
        ((uint2*)wo_f)[j] = cvt_h4(((const float4*)wo)[j]);
    }
}

// ===========================================================================
// fp16 1-term GEMM via mma.sync + cp.async. C[M,N] = A[M,1024] @ B[N,1024]^T.
// CTA tile 256x128, 512 threads (16 warps, 4m x 4n, warp tile 64x32),
// K-chunk 32, 3-stage cp.async ring, single barrier per chunk.
// MODE 0: store fp32 C. MODE 1: fused RoPE epilogue -> q hi/lo, k, v.
// ===========================================================================
#define KC 32
#define LDAS 40
#define OFF_A 0
#define OFF_B 20480                     // 256*40*2
#define STAGE_B 30720                   // + 128*40*2
#define GEMM_SMEM (3*STAGE_B)           // 92160
#define KLOG 0.28782313662f             // 2/64 * ln(10000)

template<int MODE>
__global__ __launch_bounds__(512, 1)
void gemm_fp16_kernel(const __half* __restrict__ Af, const __half* __restrict__ Bf,
                      float* __restrict__ C, const int* __restrict__ pos, int N) {
    extern __shared__ char smem[];
    const uint32_t sbase = smem_u32(smem);
    const int tid  = threadIdx.x;
    const int wid  = tid >> 5;
    const int lane = tid & 31;
    const int m0 = blockIdx.y * 256;
    const int n0 = blockIdx.x * 128;
    const int wm = wid & 3;
    const int wn = wid >> 2;

    const uint4* Ah4 = (const uint4*)Af;
    const uint4* Bh4 = (const uint4*)Bf;

    auto issue = [&](int c, int s) {
        const int k0 = c * KC;
        const uint32_t sb0 = sbase + s * STAGE_B;
#pragma unroll
        for (int it = 0; it < 2; it++) {
            int f = it * 512 + tid;
            int row = f >> 2;
            int ch  = (f & 3) * 8;
            size_t gi = ((size_t)(m0 + row) * DM + k0 + ch) >> 3;
            cp16(sb0 + OFF_A + (uint32_t)(row * LDAS + ch) * 2, Ah4 + gi);
        }
        {
            int row = tid >> 2;
            int ch  = (tid & 3) * 8;
            size_t gj = ((size_t)(n0 + row) * DM + k0 + ch) >> 3;
            cp16(sb0 + OFF_B + (uint32_t)(row * LDAS + ch) * 2, Bh4 + gj);
        }
    };

    const int gg   = lane >> 3;
    const int arow = (lane & 7) + ((lane >> 3) & 1) * 8;
    const int acol = (lane >> 4) * 8;
    const int b4row = ((gg >> 1) & 1) * 8 + (lane & 7);
    const int b4col = (gg & 1) * 8;

    float acc[4][4][4];
#pragma unroll
    for (int mi = 0; mi < 4; mi++)
#pragma unroll
        for (int ni = 0; ni < 4; ni++)
#pragma unroll
            for (int q = 0; q < 4; q++) acc[mi][ni][q] = 0.0f;

    const int nch = DM / KC;   // 32
    issue(0, 0); CP_COMMIT();
    issue(1, 1); CP_COMMIT();

    int stg_i = 0;
    for (int c = 0; c < nch; c++) {
        if (c + 1 < nch) CP_WAIT1(); else CP_WAIT0();
        __syncthreads();
        if (c + 2 < nch) { issue(c + 2, (stg_i + 2) % 3); CP_COMMIT(); }

        const uint32_t stg = sbase + stg_i * STAGE_B;
#pragma unroll
        for (int ks = 0; ks < 2; ks++) {
            uint32_t ah[4][4];
#pragma unroll
            for (int mi = 0; mi < 4; mi++) {
                uint32_t eoff = ((wm * 64 + mi * 16 + arow) * LDAS + ks * 16 + acol) * 2;
                ldsm_x4(ah[mi], stg + OFF_A + eoff);
            }
#pragma unroll
            for (int n2 = 0; n2 < 2; n2++) {
                uint32_t bhf[4];
                uint32_t eoff = ((wn * 32 + n2 * 16 + b4row) * LDAS + ks * 16 + b4col) * 2;
                ldsm_x4(bhf, stg + OFF_B + eoff);
#pragma unroll
                for (int mi = 0; mi < 4; mi++) {
                    mma16816(acc[mi][n2 * 2],     ah[mi], bhf);
                    mma16816(acc[mi][n2 * 2 + 1], ah[mi], bhf + 2);
                }
            }
        }
        stg_i = (stg_i + 1) % 3;
    }

    const int crow = lane >> 2;
    const int ccol = (lane & 3) * 2;

    if (MODE == 0) {
#pragma unroll
        for (int mi = 0; mi < 4; mi++) {
            const size_t r0 = (size_t)(m0 + wm * 64 + mi * 16 + crow);
#pragma unroll
            for (int ni = 0; ni < 4; ni++) {
                const int cc = n0 + wn * 32 + ni * 8 + ccol;
                *(float2*)(C + r0 * N + cc)       = make_float2(acc[mi][ni][0], acc[mi][ni][1]);
                *(float2*)(C + (r0 + 8) * N + cc) = make_float2(acc[mi][ni][2], acc[mi][ni][3]);
            }
        }
    } else {
        // fused RoPE: sec 0=q (rope*0.125, split hi/lo), 1=k (rope), 2=v (copy)
        const int sec  = n0 >> 10;
        const int nmod = n0 & 1023;
        int hh_[4], ii_[4];
        float ifr_[4];
#pragma unroll
        for (int ni = 0; ni < 4; ni++) {
            int colmod = nmod + wn * 32 + ni * 8 + ccol;
            hh_[ni] = colmod >> 6;
            ii_[ni] = (colmod & 63) >> 1;
            ifr_[ni] = (sec < 2) ? expf(-(float)ii_[ni] * KLOG) : 0.0f;
        }
        uint32_t* ghi = (sec == 0) ? (uint32_t*)q_hi : (sec == 1) ? (uint32_t*)k_f : (uint32_t*)v_f;
        uint32_t* glo = (uint32_t*)q_lo;
#pragma unroll
        for (int mi = 0; mi < 4; mi++) {
            const int rbase = m0 + wm * 64 + mi * 16 + crow;
#pragma unroll
            for (int half = 0; half < 2; half++) {
                const int r = rbase + half * 8;
                const int p = pos[r];
                const int b = r >> 11;
                const int s = r & 2047;
#pragma unroll
                for (int ni = 0; ni < 4; ni++) {
                    float v0 = acc[mi][ni][half * 2];
                    float v1 = acc[mi][ni][half * 2 + 1];
                    float o0, o1;
                    if (sec < 2) {
                        float ang = (float)p * ifr_[ni];
                        float cs = cosf(ang), sn = sinf(ang);
                        o0 = v0 * cs - v1 * sn;
                        o1 = v0 * sn + v1 * cs;
                        if (sec == 0) { o0 *= 0.125f; o1 *= 0.125f; }
                    } else { o0 = v0; o1 = v1; }
                    size_t idx = ((size_t)(b * HH + hh_[ni]) * SS + s) * 32 + ii_[ni];
                    if (sec == 0) {
                        uint32_t hi, lo;
                        split2(o0, o1, hi, lo);
                        ghi[idx] = hi;
                        glo[idx] = lo;
                    } else {
                        ghi[idx] = h2u(__float2half_rn(o0), __float2half_rn(o1));
                    }
                }
            }
        }
    }
}

// ===========================================================================
// Tensor-core causal flash attention: QK 2-term (q hi/lo x K), PV 1-term
// (P single-rounded x V). 3-stage cp.async KV ring, single barrier per tile.
// Output att_f single fp16.
// ===========================================================================
#define AT_LDS 72
#define AT_STG 18432                    // KV stage: Kf @0, Vf @9216
#define AT_QHI (3*AT_STG)               // 55296
#define AT_QLO (AT_QHI + 18432)
#define ATT_SMEM (AT_QLO + 18432)       // 92160

__global__ __launch_bounds__(256)
void attn_tc_kernel() {
    extern __shared__ char smem[];
    const uint32_t sb = smem_u32(smem);
    const int tid  = threadIdx.x;
    const int wid  = tid >> 5;
    const int lane = tid & 31;
    const int bh = blockIdx.y;
    const int qt = gridDim.x - 1 - blockIdx.x;   // heavy tiles first
    const int qbase = qt * 128;

    const uint4* qh4 = (const uint4*)q_hi + (size_t)bh * SS * 8;
    const uint4* ql4 = (const uint4*)q_lo + (size_t)bh * SS * 8;
    const uint4* kh4 = (const uint4*)k_f + (size_t)bh * SS * 8;
    const uint4* vh4 = (const uint4*)v_f + (size_t)bh * SS * 8;

    // ---- load Q tile 128x64 hi/lo ----
#pragma unroll
    for (int it = 0; it < 4; it++) {
        int f = it * 256 + tid;
        int row = f >> 3;
        int ch  = f & 7;
        uint32_t so = (uint32_t)(row * AT_LDS + ch * 8) * 2;
        *(uint4*)(smem + AT_QHI + so) = qh4[(size_t)(qbase + row) * 8 + ch];
        *(uint4*)(smem + AT_QLO + so) = ql4[(size_t)(qbase + row) * 8 + ch];
    }
    __syncthreads();

    const int gg   = lane >> 3;
    const int arow = (lane & 7) + ((lane >> 3) & 1) * 8;
    const int acol = (lane >> 4) * 8;
    const int b4row = ((gg >> 1) & 1) * 8 + (lane & 7);
    const int b4col = (gg & 1) * 8;
    const int v4row = (gg & 1) * 8 + (lane & 7);
    const int v4col = (gg >> 1) * 8;

    uint32_t qh[4][4], ql[4][4];
#pragma unroll
    for (int ks = 0; ks < 4; ks++) {
        uint32_t eoff = ((wid * 16 + arow) * AT_LDS + ks * 16 + acol) * 2;
        ldsm_x4(qh[ks], sb + AT_QHI + eoff);
        ldsm_x4(ql[ks], sb + AT_QLO + eoff);
    }

    float o[8][4];
#pragma unroll
    for (int ni = 0; ni < 8; ni++)
#pragma unroll
        for (int q = 0; q < 4; q++) o[ni][q] = 0.0f;
    float m0 = -INFINITY, m1 = -INFINITY, l0 = 0.0f, l1 = 0.0f;

    const int g  = lane >> 2;
    const int qq = lane & 3;
    const int row0 = qbase + wid * 16 + g;
    const int warp_maxrow = qbase + wid * 16 + 15;

    auto kv_issue = [&](int t, int s) {
        const int kvb = t * 64;
#pragma unroll
        for (int it = 0; it < 2; it++) {
            int f = it * 256 + tid;
            int row = f >> 3;
            int ch  = f & 7;
            uint32_t so = sb + s * AT_STG + (uint32_t)(row * AT_LDS + ch * 8) * 2;
            size_t gi = (size_t)(kvb + row) * 8 + ch;
            cp16(so,        kh4 + gi);
            cp16(so + 9216, vh4 + gi);
        }
    };

    const int ntiles = (qt + 1) * 2;
    kv_issue(0, 0); CP_COMMIT();
    if (ntiles > 1) { kv_issue(1, 1); CP_COMMIT(); }

    int stg_i = 0;
    for (int t = 0; t < ntiles; t++) {
        if (t + 1 < ntiles) CP_WAIT1(); else CP_WAIT0();
        __syncthreads();
        if (t + 2 < ntiles) { kv_issue(t + 2, (stg_i + 2) % 3); CP_COMMIT(); }

        const int kvb = t * 64;
        const uint32_t stg = sb + stg_i * AT_STG;

        if (kvb <= warp_maxrow) {
            // ---- S = Q @ K^T (2-term: qh,ql x K) ----
            float s[8][4];
#pragma unroll
            for (int ni = 0; ni < 8; ni++)
#pragma unroll
                for (int q = 0; q < 4; q++) s[ni][q] = 0.0f;
#pragma unroll
            for (int ks = 0; ks < 4; ks++) {
#pragma unroll
                for (int n2 = 0; n2 < 4; n2++) {
                    uint32_t khf[4];
                    uint32_t eoff = ((n2 * 16 + b4row) * AT_LDS + ks * 16 + b4col) * 2;
                    ldsm_x4(khf, stg + eoff);
                    mma16816(s[n2 * 2],     qh[ks], khf);
                    mma16816(s[n2 * 2],     ql[ks], khf);
                    mma16816(s[n2 * 2 + 1], qh[ks], khf + 2);
                    mma16816(s[n2 * 2 + 1], ql[ks], khf + 2);
                }
            }

            // ---- causal mask ----
            if (kvb + 63 > qbase + wid * 16) {
#pragma unroll
                for (int ni = 0; ni < 8; ni++) {
                    int c = kvb + ni * 8 + qq * 2;
                    if (c     > row0)     s[ni][0] = -INFINITY;
                    if (c + 1 > row0)     s[ni][1] = -INFINITY;
                    if (c     > row0 + 8) s[ni][2] = -INFINITY;
                    if (c + 1 > row0 + 8) s[ni][3] = -INFINITY;
                }
            }

            // ---- online softmax ----
            float t0 = -INFINITY, t1 = -INFINITY;
#pragma unroll
            for (int ni = 0; ni < 8; ni++) {
                t0 = fmaxf(t0, fmaxf(s[ni][0], s[ni][1]));
                t1 = fmaxf(t1, fmaxf(s[ni][2], s[ni][3]));
            }
            t0 = fmaxf(t0, __shfl_xor_sync(0xFFFFFFFF, t0, 1));
            t0 = fmaxf(t0, __shfl_xor_sync(0xFFFFFFFF, t0, 2));
            t1 = fmaxf(t1, __shfl_xor_sync(0xFFFFFFFF, t1, 1));
            t1 = fmaxf(t1, __shfl_xor_sync(0xFFFFFFFF, t1, 2));
            float nm0 = fmaxf(m0, t0), nm1 = fmaxf(m1, t1);
            float sc0 = __expf(m0 - nm0), sc1 = __expf(m1 - nm1);
            m0 = nm0; m1 = nm1;
            l0 *= sc0; l1 *= sc1;
#pragma unroll
            for (int ni = 0; ni < 8; ni++) {
                o[ni][0] *= sc0; o[ni][1] *= sc0;
                o[ni][2] *= sc1; o[ni][3] *= sc1;
            }

            // ---- P = exp(S - m) -> single fp16 fragments ----
            uint32_t ph[8][2];
            float rs0 = 0.0f, rs1 = 0.0f;
#pragma unroll
            for (int ni = 0; ni < 8; ni++) {
                float p0 = __expf(s[ni][0] - m0);
                float p1 = __expf(s[ni][1] - m0);
                float p2 = __expf(s[ni][2] - m1);
                float p3 = __expf(s[ni][3] - m1);
                rs0 += p0 + p1;
                rs1 += p2 + p3;
                ph[ni][0] = h2u(__float2half_rn(p0), __float2half_rn(p1));
                ph[ni][1] = h2u(__float2half_rn(p2), __float2half_rn(p3));
            }
            rs0 += __shfl_xor_sync(0xFFFFFFFF, rs0, 1);
            rs0 += __shfl_xor_sync(0xFFFFFFFF, rs0, 2);
            rs1 += __shfl_xor_sync(0xFFFFFFFF, rs1, 1);
            rs1 += __shfl_xor_sync(0xFFFFFFFF, rs1, 2);
            l0 += rs0; l1 += rs1;

            // ---- O += P @ V (1-term) ----
#pragma unroll
            for (int kc = 0; kc < 4; kc++) {
                uint32_t ah[4] = { ph[2*kc][0], ph[2*kc][1], ph[2*kc+1][0], ph[2*kc+1][1] };
#pragma unroll
                for (int n2 = 0; n2 < 4; n2++) {
                    uint32_t vhf[4];
                    uint32_t eoff = ((kc * 16 + v4row) * AT_LDS + n2 * 16 + v4col) * 2;
                    ldsm_x4t(vhf, stg + 9216 + eoff);
                    mma16816(o[n2 * 2],     ah, vhf);
                    mma16816(o[n2 * 2 + 1], ah, vhf + 2);
                }
            }
        }
        stg_i = (stg_i + 1) % 3;
    }

    // ---- epilogue: normalize -> att_f single fp16 ----
    const float inv0 = 1.0f / l0;
    const float inv1 = 1.0f / l1;
    const int b = bh / HH;
    const int h = bh % HH;
    uint32_t* af32 = (uint32_t*)att_f;
    const size_t base0 = ((size_t)b * SS + row0) * 512 + h * 32;
    const size_t base1 = ((size_t)b * SS + row0 + 8) * 512 + h * 32;
#pragma unroll
    for (int ni = 0; ni < 8; ni++) {
        af32[base0 + ni * 4 + qq] = h2u(__float2half_rn(o[ni][0] * inv0),
                                        __float2half_rn(o[ni][1] * inv0));
        af32[base1 + ni * 4 + qq] = h2u(__float2half_rn(o[ni][2] * inv1),
                                        __float2half_rn(o[ni][3] * inv1));
    }
}

// ===========================================================================
extern "C" void kernel_launch(void* const* d_in, const int* in_sizes, int n_in,
                              void* d_out, int out_size) {
    const float* x     = (const float*)d_in[0];
    const int*   pos   = (const int*)d_in[1];
    const float* qkv_w = (const float*)d_in[2];
    const float* out_w = (const float*)d_in[3];
    float* out = (float*)d_out;

    __half *p_x, *p_wq, *p_wo, *p_att;
    cudaGetSymbolAddress((void**)&p_x,   x_f);
    cudaGetSymbolAddress((void**)&p_wq,  wq_f);
    cudaGetSymbolAddress((void**)&p_wo,  wo_f);
    cudaGetSymbolAddress((void**)&p_att, att_f);

    cudaFuncSetAttribute(gemm_fp16_kernel<0>, cudaFuncAttributeMaxDynamicSharedMemorySize, GEMM_SMEM);
    cudaFuncSetAttribute(gemm_fp16_kernel<1>, cudaFuncAttributeMaxDynamicSharedMemorySize, GEMM_SMEM);
    cudaFuncSetAttribute(attn_tc_kernel,      cudaFuncAttributeMaxDynamicSharedMemorySize, ATT_SMEM);

    // 0) fp32 -> fp16 single-rounded x, wq, wo
    cvt_split_kernel<<<(N4_TOTAL + 255) / 256, 256>>>(x, qkv_w, out_w);

    // 1) QKV projection (1-term) + fused RoPE -> q hi/lo, k, v
    gemm_fp16_kernel<1><<<dim3(QKVN / 128, BSROWS / 256), 512, GEMM_SMEM>>>(
        p_x, p_wq, nullptr, pos, QKVN);

    // 2) Causal flash attention (QK 2-term, PV 1-term) -> att_f
    attn_tc_kernel<<<dim3(SS / 128, BB * HH), 256, ATT_SMEM>>>();

    // 3) Output projection (1-term) -> fp32 out
    gemm_fp16_kernel<0><<<dim3(DM / 128, BSROWS / 256), 512, GEMM_SMEM>>>(
        p_att, p_wo, out, nullptr, DM);
}

// round 15
// speedup vs baseline: 2.1650x; 1.1382x over previous
#include <cuda_runtime.h>
#include <cuda_fp16.h>
#include <math.h>
#include <stdint.h>

#define BB 2
#define SS 2048
#define DM 1024
#define HH 16
#define DK 64
#define BSROWS (BB*SS)      // 4096
#define QKVN (3*DM)         // 3072

// ===========================================================================
// Scratch (allocation-free rule: __device__ globals).
// fp16 single-rounded: x, weights, k, v, att, P. fp16 hi/lo split: q only.
// ===========================================================================
__device__ __align__(16) __half x_f[(size_t)BSROWS*DM];
__device__ __align__(16) __half wq_f[(size_t)QKVN*DM];
__device__ __align__(16) __half wo_f[(size_t)DM*DM];
__device__ __align__(16) __half q_hi[(size_t)BB*HH*SS*DK];
__device__ __align__(16) __half q_lo[(size_t)BB*HH*SS*DK];
__device__ __align__(16) __half k_f[(size_t)BB*HH*SS*DK];
__device__ __align__(16) __half v_f[(size_t)BB*HH*SS*DK];
__device__ __align__(16) __half att_f[(size_t)BSROWS*DM];

// ===========================================================================
// PTX helpers
// ===========================================================================
__device__ __forceinline__ uint32_t smem_u32(const void* p) {
    uint32_t a;
    asm("{ .reg .u64 t; cvta.to.shared.u64 t, %1; cvt.u32.u64 %0, t; }" : "=r"(a) : "l"(p));
    return a;
}
__device__ __forceinline__ void ldsm_x4(uint32_t* r, uint32_t addr) {
    asm volatile("ldmatrix.sync.aligned.m8n8.x4.shared.b16 {%0,%1,%2,%3}, [%4];"
                 : "=r"(r[0]), "=r"(r[1]), "=r"(r[2]), "=r"(r[3]) : "r"(addr));
}
__device__ __forceinline__ void ldsm_x4t(uint32_t* r, uint32_t addr) {
    asm volatile("ldmatrix.sync.aligned.m8n8.x4.trans.shared.b16 {%0,%1,%2,%3}, [%4];"
                 : "=r"(r[0]), "=r"(r[1]), "=r"(r[2]), "=r"(r[3]) : "r"(addr));
}
__device__ __forceinline__ void mma16816(float* d, const uint32_t* a, const uint32_t* b) {
    asm volatile("mma.sync.aligned.m16n8k16.row.col.f32.f16.f16.f32 "
                 "{%0,%1,%2,%3}, {%4,%5,%6,%7}, {%8,%9}, {%0,%1,%2,%3};"
                 : "+f"(d[0]), "+f"(d[1]), "+f"(d[2]), "+f"(d[3])
                 : "r"(a[0]), "r"(a[1]), "r"(a[2]), "r"(a[3]), "r"(b[0]), "r"(b[1]));
}
__device__ __forceinline__ void cp16(uint32_t saddr, const void* g) {
    asm volatile("cp.async.cg.shared.global [%0], [%1], 16;" :: "r"(saddr), "l"(g));
}
#define CP_COMMIT() asm volatile("cp.async.commit_group;" ::: "memory")
#define CP_WAIT1()  asm volatile("cp.async.wait_group 1;" ::: "memory")
#define CP_WAIT0()  asm volatile("cp.async.wait_group 0;" ::: "memory")

__device__ __forceinline__ uint32_t h2u(__half a, __half b) {
    __half2 t; t.x = a; t.y = b;
    return *reinterpret_cast<uint32_t*>(&t);
}
__device__ __forceinline__ uint2 cvt_h4(float4 v) {
    return make_uint2(h2u(__float2half_rn(v.x), __float2half_rn(v.y)),
                      h2u(__float2half_rn(v.z), __float2half_rn(v.w)));
}
__device__ __forceinline__ void split2(float a, float b, uint32_t& hi, uint32_t& lo) {
    __half h0 = __float2half_rn(a), h1 = __float2half_rn(b);
    __half l0 = __float2half_rn(a - __half2float(h0));
    __half l1 = __float2half_rn(b - __half2float(h1));
    hi = h2u(h0, h1);
    lo = h2u(l0, l1);
}

// ===========================================================================
// Convert: x, wq, wo -> single fp16
// ===========================================================================
#define N4_X  (BSROWS*DM/4)
#define N4_WQ (QKVN*DM/4)
#define N4_WO (DM*DM/4)
#define N4_TOTAL (N4_X + N4_WQ + N4_WO)

__global__ __launch_bounds__(256)
void cvt_split_kernel(const float* __restrict__ x, const float* __restrict__ wq,
                      const float* __restrict__ wo) {
    int i = blockIdx.x * blockDim.x + threadIdx.x;
    if (i < N4_X) {
        ((uint2*)x_f)[i] = cvt_h4(((const float4*)x)[i]);
    } else if (i < N4_X + N4_WQ) {
        int j = i - N4_X;
        ((uint2*)wq_f)[j] = cvt_h4(((const float4*)wq)[j]);
    } else if (i < N4_TOTAL) {
        int j = i - N4_X - N4_WQ;
        ((uint2*)wo_f)[j] = cvt_h4(((const float4*)wo)[j]);
    }
}

// ===========================================================================
// fp16 1-term GEMM via mma.sync + cp.async. C[M,N] = A[M,1024] @ B[N,1024]^T.
// CTA tile 256x128, 512 threads (16 warps, 4m x 4n, warp tile 64x32),
// K-chunk 64 (16 chunks, half the barriers), 3-stage ring, 1 barrier/chunk.
// MODE 0: store fp32 C. MODE 1: fused RoPE epilogue -> q hi/lo, k, v.
// ===========================================================================
#define KC 64
#define LDAS 72                         // 64 + 8 halfs padding
#define OFF_A 0
#define OFF_B 36864                     // 256*72*2
#define STAGE_B 55296                   // + 128*72*2
#define GEMM_SMEM (3*STAGE_B)           // 165888
#define KLOG 0.28782313662f             // 2/64 * ln(10000)

template<int MODE>
__global__ __launch_bounds__(512, 1)
void gemm_fp16_kernel(const __half* __restrict__ Af, const __half* __restrict__ Bf,
                      float* __restrict__ C, const int* __restrict__ pos, int N) {
    extern __shared__ char smem[];
    const uint32_t sbase = smem_u32(smem);
    const int tid  = threadIdx.x;
    const int wid  = tid >> 5;
    const int lane = tid & 31;
    const int m0 = blockIdx.y * 256;
    const int n0 = blockIdx.x * 128;
    const int wm = wid & 3;
    const int wn = wid >> 2;

    const uint4* Ah4 = (const uint4*)Af;
    const uint4* Bh4 = (const uint4*)Bf;

    // loader: A 256x64 = 2048 uint4 (4/thread), B 128x64 = 1024 uint4 (2/thread)
    auto issue = [&](int c, int s) {
        const int k0 = c * KC;
        const uint32_t sb0 = sbase + s * STAGE_B;
#pragma unroll
        for (int it = 0; it < 4; it++) {
            int f = it * 512 + tid;
            int row = f >> 3;
            int ch  = (f & 7) * 8;
            size_t gi = ((size_t)(m0 + row) * DM + k0 + ch) >> 3;
            cp16(sb0 + OFF_A + (uint32_t)(row * LDAS + ch) * 2, Ah4 + gi);
        }
#pragma unroll
        for (int it = 0; it < 2; it++) {
            int f = it * 512 + tid;
            int row = f >> 3;
            int ch  = (f & 7) * 8;
            size_t gj = ((size_t)(n0 + row) * DM + k0 + ch) >> 3;
            cp16(sb0 + OFF_B + (uint32_t)(row * LDAS + ch) * 2, Bh4 + gj);
        }
    };

    const int gg   = lane >> 3;
    const int arow = (lane & 7) + ((lane >> 3) & 1) * 8;
    const int acol = (lane >> 4) * 8;
    const int b4row = ((gg >> 1) & 1) * 8 + (lane & 7);
    const int b4col = (gg & 1) * 8;

    float acc[4][4][4];
#pragma unroll
    for (int mi = 0; mi < 4; mi++)
#pragma unroll
        for (int ni = 0; ni < 4; ni++)
#pragma unroll
            for (int q = 0; q < 4; q++) acc[mi][ni][q] = 0.0f;

    const int nch = DM / KC;   // 16
    issue(0, 0); CP_COMMIT();
    issue(1, 1); CP_COMMIT();

    int stg_i = 0;
    for (int c = 0; c < nch; c++) {
        if (c + 1 < nch) CP_WAIT1(); else CP_WAIT0();
        __syncthreads();
        if (c + 2 < nch) { issue(c + 2, (stg_i + 2) % 3); CP_COMMIT(); }

        const uint32_t stg = sbase + stg_i * STAGE_B;
#pragma unroll
        for (int ks = 0; ks < 4; ks++) {
            uint32_t ah[4][4];
#pragma unroll
            for (int mi = 0; mi < 4; mi++) {
                uint32_t eoff = ((wm * 64 + mi * 16 + arow) * LDAS + ks * 16 + acol) * 2;
                ldsm_x4(ah[mi], stg + OFF_A + eoff);
            }
#pragma unroll
            for (int n2 = 0; n2 < 2; n2++) {
                uint32_t bhf[4];
                uint32_t eoff = ((wn * 32 + n2 * 16 + b4row) * LDAS + ks * 16 + b4col) * 2;
                ldsm_x4(bhf, stg + OFF_B + eoff);
#pragma unroll
                for (int mi = 0; mi < 4; mi++) {
                    mma16816(acc[mi][n2 * 2],     ah[mi], bhf);
                    mma16816(acc[mi][n2 * 2 + 1], ah[mi], bhf + 2);
                }
            }
        }
        stg_i = (stg_i + 1) % 3;
    }

    const int crow = lane >> 2;
    const int ccol = (lane & 3) * 2;

    if (MODE == 0) {
#pragma unroll
        for (int mi = 0; mi < 4; mi++) {
            const size_t r0 = (size_t)(m0 + wm * 64 + mi * 16 + crow);
#pragma unroll
            for (int ni = 0; ni < 4; ni++) {
                const int cc = n0 + wn * 32 + ni * 8 + ccol;
                *(float2*)(C + r0 * N + cc)       = make_float2(acc[mi][ni][0], acc[mi][ni][1]);
                *(float2*)(C + (r0 + 8) * N + cc) = make_float2(acc[mi][ni][2], acc[mi][ni][3]);
            }
        }
    } else {
        // fused RoPE: sec 0=q (rope*0.125, split hi/lo), 1=k (rope), 2=v (copy)
        const int sec  = n0 >> 10;
        const int nmod = n0 & 1023;
        int hh_[4], ii_[4];
        float ifr_[4];
#pragma unroll
        for (int ni = 0; ni < 4; ni++) {
            int colmod = nmod + wn * 32 + ni * 8 + ccol;
            hh_[ni] = colmod >> 6;
            ii_[ni] = (colmod & 63) >> 1;
            ifr_[ni] = (sec < 2) ? expf(-(float)ii_[ni] * KLOG) : 0.0f;
        }
        uint32_t* ghi = (sec == 0) ? (uint32_t*)q_hi : (sec == 1) ? (uint32_t*)k_f : (uint32_t*)v_f;
        uint32_t* glo = (uint32_t*)q_lo;
#pragma unroll
        for (int mi = 0; mi < 4; mi++) {
            const int rbase = m0 + wm * 64 + mi * 16 + crow;
#pragma unroll
            for (int half = 0; half < 2; half++) {
                const int r = rbase + half * 8;
                const int p = pos[r];
                const int b = r >> 11;
                const int s = r & 2047;
#pragma unroll
                for (int ni = 0; ni < 4; ni++) {
                    float v0 = acc[mi][ni][half * 2];
                    float v1 = acc[mi][ni][half * 2 + 1];
                    float o0, o1;
                    if (sec < 2) {
                        float ang = (float)p * ifr_[ni];
                        float cs = cosf(ang), sn = sinf(ang);
                        o0 = v0 * cs - v1 * sn;
                        o1 = v0 * sn + v1 * cs;
                        if (sec == 0) { o0 *= 0.125f; o1 *= 0.125f; }
                    } else { o0 = v0; o1 = v1; }
                    size_t idx = ((size_t)(b * HH + hh_[ni]) * SS + s) * 32 + ii_[ni];
                    if (sec == 0) {
                        uint32_t hi, lo;
                        split2(o0, o1, hi, lo);
                        ghi[idx] = hi;
                        glo[idx] = lo;
                    } else {
                        ghi[idx] = h2u(__float2half_rn(o0), __float2half_rn(o1));
                    }
                }
            }
        }
    }
}

// ===========================================================================
// Tensor-core causal flash attention: QK 2-term (q hi/lo x K), PV 1-term.
// 128-row KV stages (two 64-row halves per barrier), 3-stage cp.async ring.
// ===========================================================================
#define AT_LDS 72
#define AT_HALF 9216                    // 64 rows * 72 * 2
#define AT_STG 36864                    // K 128 rows (18432) + V 128 rows
#define AT_QHI (3*AT_STG)               // 110592
#define AT_QLO (AT_QHI + 18432)
#define ATT_SMEM (AT_QLO + 18432)       // 147456

__global__ __launch_bounds__(256)
void attn_tc_kernel() {
    extern __shared__ char smem[];
    const uint32_t sb = smem_u32(smem);
    const int tid  = threadIdx.x;
    const int wid  = tid >> 5;
    const int lane = tid & 31;
    const int bh = blockIdx.y;
    const int qt = gridDim.x - 1 - blockIdx.x;   // heavy tiles first
    const int qbase = qt * 128;

    const uint4* qh4 = (const uint4*)q_hi + (size_t)bh * SS * 8;
    const uint4* ql4 = (const uint4*)q_lo + (size_t)bh * SS * 8;
    const uint4* kh4 = (const uint4*)k_f + (size_t)bh * SS * 8;
    const uint4* vh4 = (const uint4*)v_f + (size_t)bh * SS * 8;

    // ---- load Q tile 128x64 hi/lo ----
#pragma unroll
    for (int it = 0; it < 4; it++) {
        int f = it * 256 + tid;
        int row = f >> 3;
        int ch  = f & 7;
        uint32_t so = (uint32_t)(row * AT_LDS + ch * 8) * 2;
        *(uint4*)(smem + AT_QHI + so) = qh4[(size_t)(qbase + row) * 8 + ch];
        *(uint4*)(smem + AT_QLO + so) = ql4[(size_t)(qbase + row) * 8 + ch];
    }
    __syncthreads();

    const int gg   = lane >> 3;
    const int arow = (lane & 7) + ((lane >> 3) & 1) * 8;
    const int acol = (lane >> 4) * 8;
    const int b4row = ((gg >> 1) & 1) * 8 + (lane & 7);
    const int b4col = (gg & 1) * 8;
    const int v4row = (gg & 1) * 8 + (lane & 7);
    const int v4col = (gg >> 1) * 8;

    uint32_t qh[4][4], ql[4][4];
#pragma unroll
    for (int ks = 0; ks < 4; ks++) {
        uint32_t eoff = ((wid * 16 + arow) * AT_LDS + ks * 16 + acol) * 2;
        ldsm_x4(qh[ks], sb + AT_QHI + eoff);
        ldsm_x4(ql[ks], sb + AT_QLO + eoff);
    }

    float o[8][4];
#pragma unroll
    for (int ni = 0; ni < 8; ni++)
#pragma unroll
        for (int q = 0; q < 4; q++) o[ni][q] = 0.0f;
    float m0 = -INFINITY, m1 = -INFINITY, l0 = 0.0f, l1 = 0.0f;

    const int g  = lane >> 2;
    const int qq = lane & 3;
    const int row0 = qbase + wid * 16 + g;
    const int warp_maxrow = qbase + wid * 16 + 15;

    // stage loader: 128 kv rows; K 1024 uint4 (4/thread), V likewise
    auto kv_issue = [&](int t, int s) {
        const int kvb = t * 128;
#pragma unroll
        for (int it = 0; it < 4; it++) {
            int f = it * 256 + tid;
            int row = f >> 3;
            int ch  = f & 7;
            uint32_t so = sb + s * AT_STG + (uint32_t)(row * AT_LDS + ch * 8) * 2;
            size_t gi = (size_t)(kvb + row) * 8 + ch;
            cp16(so,         kh4 + gi);
            cp16(so + 18432, vh4 + gi);
        }
    };

    const int ntiles = qt + 1;                 // 128-row stages
    kv_issue(0, 0); CP_COMMIT();
    if (ntiles > 1) { kv_issue(1, 1); CP_COMMIT(); }

    int stg_i = 0;
    for (int t = 0; t < ntiles; t++) {
        if (t + 1 < ntiles) CP_WAIT1(); else CP_WAIT0();
        __syncthreads();
        if (t + 2 < ntiles) { kv_issue(t + 2, (stg_i + 2) % 3); CP_COMMIT(); }

        const uint32_t stg = sb + stg_i * AT_STG;

#pragma unroll
        for (int half = 0; half < 2; half++) {
            const int kvb = t * 128 + half * 64;
            if (kvb > warp_maxrow) break;
            const uint32_t kbase = stg + half * AT_HALF;
            const uint32_t vbase = stg + 18432 + half * AT_HALF;

            // ---- S = Q @ K^T (2-term: qh,ql x K) ----
            float s[8][4];
#pragma unroll
            for (int ni = 0; ni < 8; ni++)
#pragma unroll
                for (int q = 0; q < 4; q++) s[ni][q] = 0.0f;
#pragma unroll
            for (int ks = 0; ks < 4; ks++) {
#pragma unroll
                for (int n2 = 0; n2 < 4; n2++) {
                    uint32_t khf[4];
                    uint32_t eoff = ((n2 * 16 + b4row) * AT_LDS + ks * 16 + b4col) * 2;
                    ldsm_x4(khf, kbase + eoff);
                    mma16816(s[n2 * 2],     qh[ks], khf);
                    mma16816(s[n2 * 2],     ql[ks], khf);
                    mma16816(s[n2 * 2 + 1], qh[ks], khf + 2);
                    mma16816(s[n2 * 2 + 1], ql[ks], khf + 2);
                }
            }

            // ---- causal mask ----
            if (kvb + 63 > qbase + wid * 16) {
#pragma unroll
                for (int ni = 0; ni < 8; ni++) {
                    int c = kvb + ni * 8 + qq * 2;
                    if (c     > row0)     s[ni][0] = -INFINITY;
                    if (c + 1 > row0)     s[ni][1] = -INFINITY;
                    if (c     > row0 + 8) s[ni][2] = -INFINITY;
                    if (c + 1 > row0 + 8) s[ni][3] = -INFINITY;
                }
            }

            // ---- online softmax ----
            float t0 = -INFINITY, t1 = -INFINITY;
#pragma unroll
            for (int ni = 0; ni < 8; ni++) {
                t0 = fmaxf(t0, fmaxf(s[ni][0], s[ni][1]));
                t1 = fmaxf(t1, fmaxf(s[ni][2], s[ni][3]));
            }
            t0 = fmaxf(t0, __shfl_xor_sync(0xFFFFFFFF, t0, 1));
            t0 = fmaxf(t0, __shfl_xor_sync(0xFFFFFFFF, t0, 2));
            t1 = fmaxf(t1, __shfl_xor_sync(0xFFFFFFFF, t1, 1));
            t1 = fmaxf(t1, __shfl_xor_sync(0xFFFFFFFF, t1, 2));
            float nm0 = fmaxf(m0, t0), nm1 = fmaxf(m1, t1);
            float sc0 = __expf(m0 - nm0), sc1 = __expf(m1 - nm1);
            m0 = nm0; m1 = nm1;
            l0 *= sc0; l1 *= sc1;
#pragma unroll
            for (int ni = 0; ni < 8; ni++) {
                o[ni][0] *= sc0; o[ni][1] *= sc0;
                o[ni][2] *= sc1; o[ni][3] *= sc1;
            }

            // ---- P = exp(S - m) -> single fp16 fragments ----
            uint32_t ph[8][2];
            float rs0 = 0.0f, rs1 = 0.0f;
#pragma unroll
            for (int ni = 0; ni < 8; ni++) {
                float p0 = __expf(s[ni][0] - m0);
                float p1 = __expf(s[ni][1] - m0);
                float p2 = __expf(s[ni][2] - m1);
                float p3 = __expf(s[ni][3] - m1);
                rs0 += p0 + p1;
                rs1 += p2 + p3;
                ph[ni][0] = h2u(__float2half_rn(p0), __float2half_rn(p1));
                ph[ni][1] = h2u(__float2half_rn(p2), __float2half_rn(p3));
            }
            rs0 += __shfl_xor_sync(0xFFFFFFFF, rs0, 1);
            rs0 += __shfl_xor_sync(0xFFFFFFFF, rs0, 2);
            rs1 += __shfl_xor_sync(0xFFFFFFFF, rs1, 1);
            rs1 += __shfl_xor_sync(0xFFFFFFFF, rs1, 2);
            l0 += rs0; l1 += rs1;

            // ---- O += P @ V (1-term) ----
#pragma unroll
            for (int kc = 0; kc < 4; kc++) {
                uint32_t ah[4] = { ph[2*kc][0], ph[2*kc][1], ph[2*kc+1][0], ph[2*kc+1][1] };
#pragma unroll
                for (int n2 = 0; n2 < 4; n2++) {
                    uint32_t vhf[4];
                    uint32_t eoff = ((kc * 16 + v4row) * AT_LDS + n2 * 16 + v4col) * 2;
                    ldsm_x4t(vhf, vbase + eoff);
                    mma16816(o[n2 * 2],     ah, vhf);
                    mma16816(o[n2 * 2 + 1], ah, vhf + 2);
                }
            }
        }
        stg_i = (stg_i + 1) % 3;
    }

    // ---- epilogue: normalize -> att_f single fp16 ----
    const float inv0 = 1.0f / l0;
    const float inv1 = 1.0f / l1;
    const int b = bh / HH;
    const int h = bh % HH;
    uint32_t* af32 = (uint32_t*)att_f;
    const size_t base0 = ((size_t)b * SS + row0) * 512 + h * 32;
    const size_t base1 = ((size_t)b * SS + row0 + 8) * 512 + h * 32;
#pragma unroll
    for (int ni = 0; ni < 8; ni++) {
        af32[base0 + ni * 4 + qq] = h2u(__float2half_rn(o[ni][0] * inv0),
                                        __float2half_rn(o[ni][1] * inv0));
        af32[base1 + ni * 4 + qq] = h2u(__float2half_rn(o[ni][2] * inv1),
                                        __float2half_rn(o[ni][3] * inv1));
    }
}

// ===========================================================================
extern "C" void kernel_launch(void* const* d_in, const int* in_sizes, int n_in,
                              void* d_out, int out_size) {
    const float* x     = (const float*)d_in[0];
    const int*   pos   = (const int*)d_in[1];
    const float* qkv_w = (const float*)d_in[2];
    const float* out_w = (const float*)d_in[3];
    float* out = (float*)d_out;

    __half *p_x, *p_wq, *p_wo, *p_att;
    cudaGetSymbolAddress((void**)&p_x,   x_f);
    cudaGetSymbolAddress((void**)&p_wq,  wq_f);
    cudaGetSymbolAddress((void**)&p_wo,  wo_f);
    cudaGetSymbolAddress((void**)&p_att, att_f);

    cudaFuncSetAttribute(gemm_fp16_kernel<0>, cudaFuncAttributeMaxDynamicSharedMemorySize, GEMM_SMEM);
    cudaFuncSetAttribute(gemm_fp16_kernel<1>, cudaFuncAttributeMaxDynamicSharedMemorySize, GEMM_SMEM);
    cudaFuncSetAttribute(attn_tc_kernel,      cudaFuncAttributeMaxDynamicSharedMemorySize, ATT_SMEM);

    // 0) fp32 -> fp16 single-rounded x, wq, wo
    cvt_split_kernel<<<(N4_TOTAL + 255) / 256, 256>>>(x, qkv_w, out_w);

    // 1) QKV projection (1-term) + fused RoPE -> q hi/lo, k, v
    gemm_fp16_kernel<1><<<dim3(QKVN / 128, BSROWS / 256), 512, GEMM_SMEM>>>(
        p_x, p_wq, nullptr, pos, QKVN);

    // 2) Causal flash attention (QK 2-term, PV 1-term) -> att_f
    attn_tc_kernel<<<dim3(SS / 128, BB * HH), 256, ATT_SMEM>>>();

    // 3) Output projection (1-term) -> fp32 out
    gemm_fp16_kernel<0><<<dim3(DM / 128, BSROWS / 256), 512, GEMM_SMEM>>>(
        p_att, p_wo, out, nullptr, DM);
}

// round 16
// speedup vs baseline: 2.3328x; 1.0775x over previous
#include <cuda_runtime.h>
#include <cuda_fp16.h>
#include <math.h>
#include <stdint.h>

#define BB 2
#define SS 2048
#define DM 1024
#define HH 16
#define DK 64
#define BSROWS (BB*SS)      // 4096
#define QKVN (3*DM)         // 3072

// ===========================================================================
// Scratch (allocation-free rule: __device__ globals).
// All tensor-core operands single-rounded fp16 (error budget audited:
// each single-rounding adds ~2.4e-4 in quadrature; total ~6.7e-4 < 1e-3).
// ===========================================================================
__device__ __align__(16) __half x_f[(size_t)BSROWS*DM];
__device__ __align__(16) __half wq_f[(size_t)QKVN*DM];
__device__ __align__(16) __half wo_f[(size_t)DM*DM];
__device__ __align__(16) __half q_f[(size_t)BB*HH*SS*DK];
__device__ __align__(16) __half k_f[(size_t)BB*HH*SS*DK];
__device__ __align__(16) __half v_f[(size_t)BB*HH*SS*DK];
__device__ __align__(16) __half att_f[(size_t)BSROWS*DM];

// ===========================================================================
// PTX helpers
// ===========================================================================
__device__ __forceinline__ uint32_t smem_u32(const void* p) {
    uint32_t a;
    asm("{ .reg .u64 t; cvta.to.shared.u64 t, %1; cvt.u32.u64 %0, t; }" : "=r"(a) : "l"(p));
    return a;
}
__device__ __forceinline__ void ldsm_x4(uint32_t* r, uint32_t addr) {
    asm volatile("ldmatrix.sync.aligned.m8n8.x4.shared.b16 {%0,%1,%2,%3}, [%4];"
                 : "=r"(r[0]), "=r"(r[1]), "=r"(r[2]), "=r"(r[3]) : "r"(addr));
}
__device__ __forceinline__ void ldsm_x4t(uint32_t* r, uint32_t addr) {
    asm volatile("ldmatrix.sync.aligned.m8n8.x4.trans.shared.b16 {%0,%1,%2,%3}, [%4];"
                 : "=r"(r[0]), "=r"(r[1]), "=r"(r[2]), "=r"(r[3]) : "r"(addr));
}
__device__ __forceinline__ void mma16816(float* d, const uint32_t* a, const uint32_t* b) {
    asm volatile("mma.sync.aligned.m16n8k16.row.col.f32.f16.f16.f32 "
                 "{%0,%1,%2,%3}, {%4,%5,%6,%7}, {%8,%9}, {%0,%1,%2,%3};"
                 : "+f"(d[0]), "+f"(d[1]), "+f"(d[2]), "+f"(d[3])
                 : "r"(a[0]), "r"(a[1]), "r"(a[2]), "r"(a[3]), "r"(b[0]), "r"(b[1]));
}
__device__ __forceinline__ void cp16(uint32_t saddr, const void* g) {
    asm volatile("cp.async.cg.shared.global [%0], [%1], 16;" :: "r"(saddr), "l"(g));
}
#define CP_COMMIT() asm volatile("cp.async.commit_group;" ::: "memory")
#define CP_WAIT1()  asm volatile("cp.async.wait_group 1;" ::: "memory")
#define CP_WAIT0()  asm volatile("cp.async.wait_group 0;" ::: "memory")

__device__ __forceinline__ uint32_t h2u(__half a, __half b) {
    __half2 t; t.x = a; t.y = b;
    return *reinterpret_cast<uint32_t*>(&t);
}
__device__ __forceinline__ uint2 cvt_h4(float4 v) {
    return make_uint2(h2u(__float2half_rn(v.x), __float2half_rn(v.y)),
                      h2u(__float2half_rn(v.z), __float2half_rn(v.w)));
}

// ===========================================================================
// Convert: x, wq, wo -> single fp16
// ===========================================================================
#define N4_X  (BSROWS*DM/4)
#define N4_WQ (QKVN*DM/4)
#define N4_WO (DM*DM/4)
#define N4_TOTAL (N4_X + N4_WQ + N4_WO)

__global__ __launch_bounds__(256)
void cvt_split_kernel(const float* __restrict__ x, const float* __restrict__ wq,
                      const float* __restrict__ wo) {
    int i = blockIdx.x * blockDim.x + threadIdx.x;
    if (i < N4_X) {
        ((uint2*)x_f)[i] = cvt_h4(((const float4*)x)[i]);
    } else if (i < N4_X + N4_WQ) {
        int j = i - N4_X;
        ((uint2*)wq_f)[j] = cvt_h4(((const float4*)wq)[j]);
    } else if (i < N4_TOTAL) {
        int j = i - N4_X - N4_WQ;
        ((uint2*)wo_f)[j] = cvt_h4(((const float4*)wo)[j]);
    }
}

// ===========================================================================
// fp16 1-term GEMM via mma.sync + cp.async. C[M,N] = A[M,1024] @ B[N,1024]^T.
// CTA tile 256x128, 512 threads (16 warps, 4m x 4n, warp tile 64x32),
// K-chunk 64 (16 chunks), 3-stage ring, 1 barrier/chunk.
// MODE 0: store fp32 C. MODE 1: fused RoPE epilogue -> q, k, v (fp16).
// ===========================================================================
#define KC 64
#define LDAS 72                         // 64 + 8 halfs padding
#define OFF_A 0
#define OFF_B 36864                     // 256*72*2
#define STAGE_B 55296                   // + 128*72*2
#define GEMM_SMEM (3*STAGE_B)           // 165888
#define KLOG 0.28782313662f             // 2/64 * ln(10000)

template<int MODE>
__global__ __launch_bounds__(512, 1)
void gemm_fp16_kernel(const __half* __restrict__ Af, const __half* __restrict__ Bf,
                      float* __restrict__ C, const int* __restrict__ pos, int N) {
    extern __shared__ char smem[];
    const uint32_t sbase = smem_u32(smem);
    const int tid  = threadIdx.x;
    const int wid  = tid >> 5;
    const int lane = tid & 31;
    const int m0 = blockIdx.y * 256;
    const int n0 = blockIdx.x * 128;
    const int wm = wid & 3;
    const int wn = wid >> 2;

    const uint4* Ah4 = (const uint4*)Af;
    const uint4* Bh4 = (const uint4*)Bf;

    auto issue = [&](int c, int s) {
        const int k0 = c * KC;
        const uint32_t sb0 = sbase + s * STAGE_B;
#pragma unroll
        for (int it = 0; it < 4; it++) {
            int f = it * 512 + tid;
            int row = f >> 3;
            int ch  = (f & 7) * 8;
            size_t gi = ((size_t)(m0 + row) * DM + k0 + ch) >> 3;
            cp16(sb0 + OFF_A + (uint32_t)(row * LDAS + ch) * 2, Ah4 + gi);
        }
#pragma unroll
        for (int it = 0; it < 2; it++) {
            int f = it * 512 + tid;
            int row = f >> 3;
            int ch  = (f & 7) * 8;
            size_t gj = ((size_t)(n0 + row) * DM + k0 + ch) >> 3;
            cp16(sb0 + OFF_B + (uint32_t)(row * LDAS + ch) * 2, Bh4 + gj);
        }
    };

    const int gg   = lane >> 3;
    const int arow = (lane & 7) + ((lane >> 3) & 1) * 8;
    const int acol = (lane >> 4) * 8;
    const int b4row = ((gg >> 1) & 1) * 8 + (lane & 7);
    const int b4col = (gg & 1) * 8;

    float acc[4][4][4];
#pragma unroll
    for (int mi = 0; mi < 4; mi++)
#pragma unroll
        for (int ni = 0; ni < 4; ni++)
#pragma unroll
            for (int q = 0; q < 4; q++) acc[mi][ni][q] = 0.0f;

    const int nch = DM / KC;   // 16
    issue(0, 0); CP_COMMIT();
    issue(1, 1); CP_COMMIT();

    int stg_i = 0;
    for (int c = 0; c < nch; c++) {
        if (c + 1 < nch) CP_WAIT1(); else CP_WAIT0();
        __syncthreads();
        if (c + 2 < nch) { issue(c + 2, (stg_i + 2) % 3); CP_COMMIT(); }

        const uint32_t stg = sbase + stg_i * STAGE_B;
#pragma unroll
        for (int ks = 0; ks < 4; ks++) {
            uint32_t ah[4][4];
#pragma unroll
            for (int mi = 0; mi < 4; mi++) {
                uint32_t eoff = ((wm * 64 + mi * 16 + arow) * LDAS + ks * 16 + acol) * 2;
                ldsm_x4(ah[mi], stg + OFF_A + eoff);
            }
#pragma unroll
            for (int n2 = 0; n2 < 2; n2++) {
                uint32_t bhf[4];
                uint32_t eoff = ((wn * 32 + n2 * 16 + b4row) * LDAS + ks * 16 + b4col) * 2;
                ldsm_x4(bhf, stg + OFF_B + eoff);
#pragma unroll
                for (int mi = 0; mi < 4; mi++) {
                    mma16816(acc[mi][n2 * 2],     ah[mi], bhf);
                    mma16816(acc[mi][n2 * 2 + 1], ah[mi], bhf + 2);
                }
            }
        }
        stg_i = (stg_i + 1) % 3;
    }

    const int crow = lane >> 2;
    const int ccol = (lane & 3) * 2;

    if (MODE == 0) {
#pragma unroll
        for (int mi = 0; mi < 4; mi++) {
            const size_t r0 = (size_t)(m0 + wm * 64 + mi * 16 + crow);
#pragma unroll
            for (int ni = 0; ni < 4; ni++) {
                const int cc = n0 + wn * 32 + ni * 8 + ccol;
                *(float2*)(C + r0 * N + cc)       = make_float2(acc[mi][ni][0], acc[mi][ni][1]);
                *(float2*)(C + (r0 + 8) * N + cc) = make_float2(acc[mi][ni][2], acc[mi][ni][3]);
            }
        }
    } else {
        // fused RoPE: sec 0=q (rope*0.125), 1=k (rope), 2=v (copy); all fp16
        const int sec  = n0 >> 10;
        const int nmod = n0 & 1023;
        int hh_[4], ii_[4];
        float ifr_[4];
#pragma unroll
        for (int ni = 0; ni < 4; ni++) {
            int colmod = nmod + wn * 32 + ni * 8 + ccol;
            hh_[ni] = colmod >> 6;
            ii_[ni] = (colmod & 63) >> 1;
            ifr_[ni] = (sec < 2) ? expf(-(float)ii_[ni] * KLOG) : 0.0f;
        }
        uint32_t* gdst = (sec == 0) ? (uint32_t*)q_f : (sec == 1) ? (uint32_t*)k_f : (uint32_t*)v_f;
#pragma unroll
        for (int mi = 0; mi < 4; mi++) {
            const int rbase = m0 + wm * 64 + mi * 16 + crow;
#pragma unroll
            for (int half = 0; half < 2; half++) {
                const int r = rbase + half * 8;
                const int p = pos[r];
                const int b = r >> 11;
                const int s = r & 2047;
#pragma unroll
                for (int ni = 0; ni < 4; ni++) {
                    float v0 = acc[mi][ni][half * 2];
                    float v1 = acc[mi][ni][half * 2 + 1];
                    float o0, o1;
                    if (sec < 2) {
                        float ang = (float)p * ifr_[ni];
                        float cs = cosf(ang), sn = sinf(ang);
                        o0 = v0 * cs - v1 * sn;
                        o1 = v0 * sn + v1 * cs;
                        if (sec == 0) { o0 *= 0.125f; o1 *= 0.125f; }
                    } else { o0 = v0; o1 = v1; }
                    size_t idx = ((size_t)(b * HH + hh_[ni]) * SS + s) * 32 + ii_[ni];
                    gdst[idx] = h2u(__float2half_rn(o0), __float2half_rn(o1));
                }
            }
        }
    }
}

// ===========================================================================
// Tensor-core causal flash attention: QK 1-term, PV 1-term (all fp16).
// 128-row KV stages (two 64-row halves per barrier), 3-stage cp.async ring.
// ===========================================================================
#define AT_LDS 72
#define AT_HALF 9216                    // 64 rows * 72 * 2
#define AT_STG 36864                    // K 128 rows (18432) + V 128 rows
#define AT_Q (3*AT_STG)                 // 110592
#define ATT_SMEM (AT_Q + 18432)         // 129024

__global__ __launch_bounds__(256)
void attn_tc_kernel() {
    extern __shared__ char smem[];
    const uint32_t sb = smem_u32(smem);
    const int tid  = threadIdx.x;
    const int wid  = tid >> 5;
    const int lane = tid & 31;
    const int bh = blockIdx.y;
    const int qt = gridDim.x - 1 - blockIdx.x;   // heavy tiles first
    const int qbase = qt * 128;

    const uint4* q4  = (const uint4*)q_f + (size_t)bh * SS * 8;
    const uint4* kh4 = (const uint4*)k_f + (size_t)bh * SS * 8;
    const uint4* vh4 = (const uint4*)v_f + (size_t)bh * SS * 8;

    // ---- load Q tile 128x64 ----
#pragma unroll
    for (int it = 0; it < 4; it++) {
        int f = it * 256 + tid;
        int row = f >> 3;
        int ch  = f & 7;
        uint32_t so = (uint32_t)(row * AT_LDS + ch * 8) * 2;
        *(uint4*)(smem + AT_Q + so) = q4[(size_t)(qbase + row) * 8 + ch];
    }
    __syncthreads();

    const int gg   = lane >> 3;
    const int arow = (lane & 7) + ((lane >> 3) & 1) * 8;
    const int acol = (lane >> 4) * 8;
    const int b4row = ((gg >> 1) & 1) * 8 + (lane & 7);
    const int b4col = (gg & 1) * 8;
    const int v4row = (gg & 1) * 8 + (lane & 7);
    const int v4col = (gg >> 1) * 8;

    uint32_t qh[4][4];
#pragma unroll
    for (int ks = 0; ks < 4; ks++) {
        uint32_t eoff = ((wid * 16 + arow) * AT_LDS + ks * 16 + acol) * 2;
        ldsm_x4(qh[ks], sb + AT_Q + eoff);
    }

    float o[8][4];
#pragma unroll
    for (int ni = 0; ni < 8; ni++)
#pragma unroll
        for (int q = 0; q < 4; q++) o[ni][q] = 0.0f;
    float m0 = -INFINITY, m1 = -INFINITY, l0 = 0.0f, l1 = 0.0f;

    const int g  = lane >> 2;
    const int qq = lane & 3;
    const int row0 = qbase + wid * 16 + g;
    const int warp_maxrow = qbase + wid * 16 + 15;

    auto kv_issue = [&](int t, int s) {
        const int kvb = t * 128;
#pragma unroll
        for (int it = 0; it < 4; it++) {
            int f = it * 256 + tid;
            int row = f >> 3;
            int ch  = f & 7;
            uint32_t so = sb + s * AT_STG + (uint32_t)(row * AT_LDS + ch * 8) * 2;
            size_t gi = (size_t)(kvb + row) * 8 + ch;
            cp16(so,         kh4 + gi);
            cp16(so + 18432, vh4 + gi);
        }
    };

    const int ntiles = qt + 1;                 // 128-row stages
    kv_issue(0, 0); CP_COMMIT();
    if (ntiles > 1) { kv_issue(1, 1); CP_COMMIT(); }

    int stg_i = 0;
    for (int t = 0; t < ntiles; t++) {
        if (t + 1 < ntiles) CP_WAIT1(); else CP_WAIT0();
        __syncthreads();
        if (t + 2 < ntiles) { kv_issue(t + 2, (stg_i + 2) % 3); CP_COMMIT(); }

        const uint32_t stg = sb + stg_i * AT_STG;

#pragma unroll
        for (int half = 0; half < 2; half++) {
            const int kvb = t * 128 + half * 64;
            if (kvb > warp_maxrow) break;
            const uint32_t kbase = stg + half * AT_HALF;
            const uint32_t vbase = stg + 18432 + half * AT_HALF;

            // ---- S = Q @ K^T (1-term) ----
            float s[8][4];
#pragma unroll
            for (int ni = 0; ni < 8; ni++)
#pragma unroll
                for (int q = 0; q < 4; q++) s[ni][q] = 0.0f;
#pragma unroll
            for (int ks = 0; ks < 4; ks++) {
#pragma unroll
                for (int n2 = 0; n2 < 4; n2++) {
                    uint32_t khf[4];
                    uint32_t eoff = ((n2 * 16 + b4row) * AT_LDS + ks * 16 + b4col) * 2;
                    ldsm_x4(khf, kbase + eoff);
                    mma16816(s[n2 * 2],     qh[ks], khf);
                    mma16816(s[n2 * 2 + 1], qh[ks], khf + 2);
                }
            }

            // ---- causal mask ----
            if (kvb + 63 > qbase + wid * 16) {
#pragma unroll
                for (int ni = 0; ni < 8; ni++) {
                    int c = kvb + ni * 8 + qq * 2;
                    if (c     > row0)     s[ni][0] = -INFINITY;
                    if (c + 1 > row0)     s[ni][1] = -INFINITY;
                    if (c     > row0 + 8) s[ni][2] = -INFINITY;
                    if (c + 1 > row0 + 8) s[ni][3] = -INFINITY;
                }
            }

            // ---- online softmax ----
            float t0 = -INFINITY, t1 = -INFINITY;
#pragma unroll
            for (int ni = 0; ni < 8; ni++) {
                t0 = fmaxf(t0, fmaxf(s[ni][0], s[ni][1]));
                t1 = fmaxf(t1, fmaxf(s[ni][2], s[ni][3]));
            }
            t0 = fmaxf(t0, __shfl_xor_sync(0xFFFFFFFF, t0, 1));
            t0 = fmaxf(t0, __shfl_xor_sync(0xFFFFFFFF, t0, 2));
            t1 = fmaxf(t1, __shfl_xor_sync(0xFFFFFFFF, t1, 1));
            t1 = fmaxf(t1, __shfl_xor_sync(0xFFFFFFFF, t1, 2));
            float nm0 = fmaxf(m0, t0), nm1 = fmaxf(m1, t1);
            float sc0 = __expf(m0 - nm0), sc1 = __expf(m1 - nm1);
            m0 = nm0; m1 = nm1;
            l0 *= sc0; l1 *= sc1;
#pragma unroll
            for (int ni = 0; ni < 8; ni++) {
                o[ni][0] *= sc0; o[ni][1] *= sc0;
                o[ni][2] *= sc1; o[ni][3] *= sc1;
            }

            // ---- P = exp(S - m) -> single fp16 fragments ----
            uint32_t ph[8][2];
            float rs0 = 0.0f, rs1 = 0.0f;
#pragma unroll
            for (int ni = 0; ni < 8; ni++) {
                float p0 = __expf(s[ni][0] - m0);
                float p1 = __expf(s[ni][1] - m0);
                float p2 = __expf(s[ni][2] - m1);
                float p3 = __expf(s[ni][3] - m1);
                rs0 += p0 + p1;
                rs1 += p2 + p3;
                ph[ni][0] = h2u(__float2half_rn(p0), __float2half_rn(p1));
                ph[ni][1] = h2u(__float2half_rn(p2), __float2half_rn(p3));
            }
            rs0 += __shfl_xor_sync(0xFFFFFFFF, rs0, 1);
            rs0 += __shfl_xor_sync(0xFFFFFFFF, rs0, 2);
            rs1 += __shfl_xor_sync(0xFFFFFFFF, rs1, 1);
            rs1 += __shfl_xor_sync(0xFFFFFFFF, rs1, 2);
            l0 += rs0; l1 += rs1;

            // ---- O += P @ V (1-term) ----
#pragma unroll
            for (int kc = 0; kc < 4; kc++) {
                uint32_t ah[4] = { ph[2*kc][0], ph[2*kc][1], ph[2*kc+1][0], ph[2*kc+1][1] };
#pragma unroll
                for (int n2 = 0; n2 < 4; n2++) {
                    uint32_t vhf[4];
                    uint32_t eoff = ((kc * 16 + v4row) * AT_LDS + n2 * 16 + v4col) * 2;
                    ldsm_x4t(vhf, vbase + eoff);
                    mma16816(o[n2 * 2],     ah, vhf);
                    mma16816(o[n2 * 2 + 1], ah, vhf + 2);
                }
            }
        }
        stg_i = (stg_i + 1) % 3;
    }

    // ---- epilogue: normalize -> att_f single fp16 ----
    const float inv0 = 1.0f / l0;
    const float inv1 = 1.0f / l1;
    const int b = bh / HH;
    const int h = bh % HH;
    uint32_t* af32 = (uint32_t*)att_f;
    const size_t base0 = ((size_t)b * SS + row0) * 512 + h * 32;
    const size_t base1 = ((size_t)b * SS + row0 + 8) * 512 + h * 32;
#pragma unroll
    for (int ni = 0; ni < 8; ni++) {
        af32[base0 + ni * 4 + qq] = h2u(__float2half_rn(o[ni][0] * inv0),
                                        __float2half_rn(o[ni][1] * inv0));
        af32[base1 + ni * 4 + qq] = h2u(__float2half_rn(o[ni][2] * inv1),
                                        __float2half_rn(o[ni][3] * inv1));
    }
}

// ===========================================================================
extern "C" void kernel_launch(void* const* d_in, const int* in_sizes, int n_in,
                              void* d_out, int out_size) {
    const float* x     = (const float*)d_in[0];
    const int*   pos   = (const int*)d_in[1];
    const float* qkv_w = (const float*)d_in[2];
    const float* out_w = (const float*)d_in[3];
    float* out = (float*)d_out;

    __half *p_x, *p_wq, *p_wo, *p_att;
    cudaGetSymbolAddress((void**)&p_x,   x_f);
    cudaGetSymbolAddress((void**)&p_wq,  wq_f);
    cudaGetSymbolAddress((void**)&p_wo,  wo_f);
    cudaGetSymbolAddress((void**)&p_att, att_f);

    cudaFuncSetAttribute(gemm_fp16_kernel<0>, cudaFuncAttributeMaxDynamicSharedMemorySize, GEMM_SMEM);
    cudaFuncSetAttribute(gemm_fp16_kernel<1>, cudaFuncAttributeMaxDynamicSharedMemorySize, GEMM_SMEM);
    cudaFuncSetAttribute(attn_tc_kernel,      cudaFuncAttributeMaxDynamicSharedMemorySize, ATT_SMEM);

    // 0) fp32 -> fp16 single-rounded x, wq, wo
    cvt_split_kernel<<<(N4_TOTAL + 255) / 256, 256>>>(x, qkv_w, out_w);

    // 1) QKV projection (1-term) + fused RoPE -> q, k, v (fp16)
    gemm_fp16_kernel<1><<<dim3(QKVN / 128, BSROWS / 256), 512, GEMM_SMEM>>>(
        p_x, p_wq, nullptr, pos, QKVN);

    // 2) Causal flash attention (QK 1-term, PV 1-term) -> att_f
    attn_tc_kernel<<<dim3(SS / 128, BB * HH), 256, ATT_SMEM>>>();

    // 3) Output projection (1-term) -> fp32 out
    gemm_fp16_kernel<0><<<dim3(DM / 128, BSROWS / 256), 512, GEMM_SMEM>>>(
        p_att, p_wo, out, nullptr, DM);
}